// round 1
// baseline (speedup 1.0000x reference)
#include <cuda_runtime.h>
#include <cuda_bf16.h>
#include <math.h>

// ---------------- problem constants ----------------
#define NB        2
#define D_MODEL   512
#define D_STATE   128
#define D_CONV    4
#define HEADDIM   64
#define D_INNER   1024
#define NHEADS    16
#define CONV_DIM  1280          // D_INNER + 2*D_STATE
#define D_IN_PROJ 2320          // 2*D_INNER + 2*D_STATE + NHEADS
#define LABELS    1000
#define BATCH     2
#define SEQ       512
#define MROWS     (BATCH*SEQ)   // 1024

// ---------------- scratch (no allocation allowed) ----------------
__device__ float g_x  [MROWS * D_MODEL];     // running residual stream
__device__ float g_zx [MROWS * D_IN_PROJ];   // in_proj output
__device__ float g_xbc[MROWS * CONV_DIM];    // conv+silu output
__device__ float g_dt [MROWS * NHEADS];      // softplus(dt)
__device__ float g_dA [MROWS * NHEADS];      // exp(dt*A)
__device__ float g_y  [MROWS * D_INNER];     // scan output / gated / rms'ed
__device__ float g_y2 [MROWS * D_MODEL];     // out_proj output

// ---------------- f32x2 packed helpers ----------------
__device__ __forceinline__ unsigned long long pk2(float lo, float hi) {
    unsigned long long r;
    asm("mov.b64 %0,{%1,%2};" : "=l"(r) : "f"(lo), "f"(hi));
    return r;
}
__device__ __forceinline__ void upk2(unsigned long long v, float& lo, float& hi) {
    asm("mov.b64 {%0,%1},%2;" : "=f"(lo), "=f"(hi) : "l"(v));
}
__device__ __forceinline__ unsigned long long fma2(unsigned long long a, unsigned long long b, unsigned long long c) {
    unsigned long long d;
    asm("fma.rn.f32x2 %0,%1,%2,%3;" : "=l"(d) : "l"(a), "l"(b), "l"(c));
    return d;
}
__device__ __forceinline__ unsigned long long mul2(unsigned long long a, unsigned long long b) {
    unsigned long long d;
    asm("mul.rn.f32x2 %0,%1,%2;" : "=l"(d) : "l"(a), "l"(b));
    return d;
}

// ---------------- embedding gather ----------------
__global__ void embed_kernel(const int* __restrict__ tokens,
                             const float* __restrict__ emb) {
    int idx = blockIdx.x * blockDim.x + threadIdx.x;       // over MROWS*D_MODEL
    int m = idx >> 9;          // /512
    int d = idx & 511;
    g_x[idx] = emb[(long)tokens[m] * D_MODEL + d];
}

// ---------------- fp32 tiled GEMM: C[M,N] = A[M,K] @ W[N,K]^T (+bias) ----------------
// BM=BN=64, BK=16, 256 threads, 4x4 per-thread tile. M,K multiples of 64/16; N guarded.
__global__ __launch_bounds__(256) void gemm_btn(
    const float* __restrict__ A, const float* __restrict__ W,
    const float* __restrict__ bias, float* __restrict__ C,
    int M, int N, int K)
{
    __shared__ float As[16][68];
    __shared__ float Ws[16][68];
    int tid = threadIdx.x;
    int tx = tid & 15, ty = tid >> 4;
    int rowBase = blockIdx.y * 64;
    int colBase = blockIdx.x * 64;
    int lrow = tid >> 2;             // 0..63
    int lk4  = (tid & 3) * 4;        // 0,4,8,12

    float acc[4][4];
#pragma unroll
    for (int i = 0; i < 4; i++)
#pragma unroll
        for (int j = 0; j < 4; j++) acc[i][j] = 0.f;

    for (int k0 = 0; k0 < K; k0 += 16) {
        {
            const float4 a4 = *(const float4*)(A + (long)(rowBase + lrow) * K + k0 + lk4);
            As[lk4 + 0][lrow] = a4.x; As[lk4 + 1][lrow] = a4.y;
            As[lk4 + 2][lrow] = a4.z; As[lk4 + 3][lrow] = a4.w;
        }
        {
            int wr = colBase + lrow;
            float4 w4 = make_float4(0.f, 0.f, 0.f, 0.f);
            if (wr < N) w4 = *(const float4*)(W + (long)wr * K + k0 + lk4);
            Ws[lk4 + 0][lrow] = w4.x; Ws[lk4 + 1][lrow] = w4.y;
            Ws[lk4 + 2][lrow] = w4.z; Ws[lk4 + 3][lrow] = w4.w;
        }
        __syncthreads();
#pragma unroll
        for (int k = 0; k < 16; k++) {
            float4 a4 = *(const float4*)&As[k][ty * 4];
            float4 b4 = *(const float4*)&Ws[k][tx * 4];
            float av[4] = {a4.x, a4.y, a4.z, a4.w};
            float bv[4] = {b4.x, b4.y, b4.z, b4.w};
#pragma unroll
            for (int i = 0; i < 4; i++)
#pragma unroll
                for (int j = 0; j < 4; j++)
                    acc[i][j] = fmaf(av[i], bv[j], acc[i][j]);
        }
        __syncthreads();
    }

#pragma unroll
    for (int i = 0; i < 4; i++) {
        int r = rowBase + ty * 4 + i;
#pragma unroll
        for (int j = 0; j < 4; j++) {
            int c = colBase + tx * 4 + j;
            if (c < N) {
                float v = acc[i][j];
                if (bias) v += bias[c];
                C[(long)r * N + c] = v;
            }
        }
    }
}

// ---------------- causal conv4 + bias + SiLU ----------------
__global__ void conv_silu_kernel(const float* __restrict__ cw,
                                 const float* __restrict__ cb) {
    int idx = blockIdx.x * blockDim.x + threadIdx.x;   // over MROWS*CONV_DIM
    if (idx >= MROWS * CONV_DIM) return;
    int c = idx % CONV_DIM;
    int m = idx / CONV_DIM;
    int b = m >> 9, l = m & 511;
    float acc = cb[c];
#pragma unroll
    for (int k = 0; k < D_CONV; k++) {
        int ls = l + k - (D_CONV - 1);
        if (ls >= 0)
            acc = fmaf(g_zx[(long)((b << 9) + ls) * D_IN_PROJ + D_INNER + c], cw[c * D_CONV + k], acc);
    }
    // silu
    g_xbc[idx] = acc / (1.f + __expf(-acc));
}

// ---------------- dt = softplus(raw + bias), dA = exp(dt * A) ----------------
__global__ void dt_kernel(const float* __restrict__ dtb,
                          const float* __restrict__ A_log) {
    int idx = blockIdx.x * blockDim.x + threadIdx.x;   // over MROWS*NHEADS
    if (idx >= MROWS * NHEADS) return;
    int h = idx & (NHEADS - 1);
    int m = idx >> 4;
    float v = g_zx[(long)m * D_IN_PROJ + D_INNER + CONV_DIM + h] + dtb[h];
    float dt = (v > 20.f) ? v : log1pf(expf(v));
    float A = -expf(A_log[h]);
    g_dt[idx] = dt;
    g_dA[idx] = expf(dt * A);
}

// ---------------- sequential selective scan ----------------
// One block per (b,h). 256 threads: q = t&3 owns n in [q*32, q*32+32), p = t>>2.
// State h[p][n] in registers as 16 packed f32x2. Prefetch PF steps into shared.
#define PF 8
__global__ __launch_bounds__(256) void scan_kernel(const float* __restrict__ Dv,
                                                   int layer_head_off) {
    int bh = blockIdx.x;            // 0..31
    int b = bh >> 4, h = bh & 15;
    int t = threadIdx.x;
    int q = t & 3, p = t >> 2;

    __shared__ float sB[PF][4 * 36];
    __shared__ float sC[PF][4 * 36];
    __shared__ float sx[PF][64];
    __shared__ float sdA[PF], sdt[PF];

    unsigned long long h2[16];
#pragma unroll
    for (int j = 0; j < 16; j++) h2[j] = 0ull;
    float Dval = Dv[layer_head_off + h];

    const float* xbc_b = g_xbc + (long)(b * SEQ) * CONV_DIM;

    for (int l0 = 0; l0 < SEQ; l0 += PF) {
        // stage B, C (split into per-q 36-float segments), x, scalars
        for (int i = t; i < PF * 128; i += 256) {
            int s = i >> 7, n = i & 127;
            int qq = n >> 5, j = n & 31;
            sB[s][qq * 36 + j] = xbc_b[(long)(l0 + s) * CONV_DIM + D_INNER + n];
            sC[s][qq * 36 + j] = xbc_b[(long)(l0 + s) * CONV_DIM + D_INNER + D_STATE + n];
        }
        for (int i = t; i < PF * 64; i += 256) {
            int s = i >> 6, pp = i & 63;
            sx[s][pp] = xbc_b[(long)(l0 + s) * CONV_DIM + h * HEADDIM + pp];
        }
        if (t < PF) {
            int m = b * SEQ + l0 + t;
            sdA[t] = g_dA[m * NHEADS + h];
            sdt[t] = g_dt[m * NHEADS + h];
        }
        __syncthreads();

#pragma unroll
        for (int s = 0; s < PF; s++) {
            float dA = sdA[s];
            float xv = sx[s][p];
            float coef = sdt[s] * xv;
            unsigned long long dA2 = pk2(dA, dA);
            unsigned long long cf2 = pk2(coef, coef);
            const unsigned long long* B2 = (const unsigned long long*)&sB[s][q * 36];
            const unsigned long long* C2 = (const unsigned long long*)&sC[s][q * 36];
            unsigned long long acc2 = 0ull;
#pragma unroll
            for (int jj = 0; jj < 16; jj++) {
                unsigned long long b2 = B2[jj];
                unsigned long long c2 = C2[jj];
                h2[jj] = fma2(h2[jj], dA2, mul2(cf2, b2));
                acc2 = fma2(h2[jj], c2, acc2);
            }
            float alo, ahi;
            upk2(acc2, alo, ahi);
            float acc = alo + ahi;
            acc += __shfl_xor_sync(0xffffffffu, acc, 1);
            acc += __shfl_xor_sync(0xffffffffu, acc, 2);
            if (q == 0)
                g_y[(long)(b * SEQ + l0 + s) * D_INNER + h * HEADDIM + p] = acc + Dval * xv;
        }
        __syncthreads();
    }
}

// ---------------- y *= silu(z); RMSNorm over D_INNER; *= rms_w ----------------
__global__ __launch_bounds__(256) void gate_rms_kernel(const float* __restrict__ rw) {
    int m = blockIdx.x;
    int t = threadIdx.x;
    __shared__ float red[8];
    float vals[4];
    float ss = 0.f;
#pragma unroll
    for (int i = 0; i < 4; i++) {
        int c = t + i * 256;
        float z = g_zx[(long)m * D_IN_PROJ + c];
        float gate = z / (1.f + __expf(-z));
        float v = g_y[(long)m * D_INNER + c] * gate;
        vals[i] = v;
        ss = fmaf(v, v, ss);
    }
#pragma unroll
    for (int o = 16; o; o >>= 1) ss += __shfl_xor_sync(0xffffffffu, ss, o);
    if ((t & 31) == 0) red[t >> 5] = ss;
    __syncthreads();
    float tot = 0.f;
#pragma unroll
    for (int i = 0; i < 8; i++) tot += red[i];
    float rs = rsqrtf(tot * (1.f / D_INNER) + 1e-5f);
#pragma unroll
    for (int i = 0; i < 4; i++) {
        int c = t + i * 256;
        g_y[(long)m * D_INNER + c] = vals[i] * rs * rw[c];
    }
}

// ---------------- x = LayerNorm(y2 + x) ----------------
__global__ __launch_bounds__(256) void res_ln_kernel(const float* __restrict__ lw,
                                                     const float* __restrict__ lb) {
    int m = blockIdx.x;
    int t = threadIdx.x;
    __shared__ float red[8];
    float v0 = g_y2[(long)m * D_MODEL + t]       + g_x[(long)m * D_MODEL + t];
    float v1 = g_y2[(long)m * D_MODEL + t + 256] + g_x[(long)m * D_MODEL + t + 256];
    float s = v0 + v1;
#pragma unroll
    for (int o = 16; o; o >>= 1) s += __shfl_xor_sync(0xffffffffu, s, o);
    if ((t & 31) == 0) red[t >> 5] = s;
    __syncthreads();
    float tot = 0.f;
#pragma unroll
    for (int i = 0; i < 8; i++) tot += red[i];
    float mu = tot * (1.f / D_MODEL);
    __syncthreads();
    float c0 = v0 - mu, c1 = v1 - mu;
    float ss = c0 * c0 + c1 * c1;
#pragma unroll
    for (int o = 16; o; o >>= 1) ss += __shfl_xor_sync(0xffffffffu, ss, o);
    if ((t & 31) == 0) red[t >> 5] = ss;
    __syncthreads();
    float vtot = 0.f;
#pragma unroll
    for (int i = 0; i < 8; i++) vtot += red[i];
    float rs = rsqrtf(vtot * (1.f / D_MODEL) + 1e-5f);
    g_x[(long)m * D_MODEL + t]       = c0 * rs * lw[t]       + lb[t];
    g_x[(long)m * D_MODEL + t + 256] = c1 * rs * lw[t + 256] + lb[t + 256];
}

// ---------------- launch ----------------
extern "C" void kernel_launch(void* const* d_in, const int* in_sizes, int n_in,
                              void* d_out, int out_size) {
    const int*   tokens    = (const int*)  d_in[0];
    const float* embedding = (const float*)d_in[1];
    const float* in_proj_w = (const float*)d_in[2];
    const float* conv_w    = (const float*)d_in[3];
    const float* conv_b    = (const float*)d_in[4];
    const float* dt_bias   = (const float*)d_in[5];
    const float* A_log     = (const float*)d_in[6];
    const float* Dv        = (const float*)d_in[7];
    const float* rms_w     = (const float*)d_in[8];
    const float* out_proj_w= (const float*)d_in[9];
    const float* ln_w      = (const float*)d_in[10];
    const float* ln_b      = (const float*)d_in[11];
    const float* head_w    = (const float*)d_in[12];
    const float* head_b    = (const float*)d_in[13];
    float* out = (float*)d_out;

    void *p_x, *p_zx, *p_y, *p_y2;
    cudaGetSymbolAddress(&p_x,  g_x);
    cudaGetSymbolAddress(&p_zx, g_zx);
    cudaGetSymbolAddress(&p_y,  g_y);
    cudaGetSymbolAddress(&p_y2, g_y2);
    float* dx  = (float*)p_x;
    float* dzx = (float*)p_zx;
    float* dy  = (float*)p_y;
    float* dy2 = (float*)p_y2;

    // embedding
    embed_kernel<<<(MROWS * D_MODEL) / 256, 256>>>(tokens, embedding);

    for (int i = 0; i < NB; i++) {
        // in_proj: (1024,2320) = x (1024,512) @ Wi^T
        {
            dim3 grid((D_IN_PROJ + 63) / 64, MROWS / 64);
            gemm_btn<<<grid, 256>>>(dx, in_proj_w + (long)i * D_IN_PROJ * D_MODEL,
                                    nullptr, dzx, MROWS, D_IN_PROJ, D_MODEL);
        }
        // conv + silu
        conv_silu_kernel<<<(MROWS * CONV_DIM + 255) / 256, 256>>>(
            conv_w + (long)i * CONV_DIM * D_CONV, conv_b + (long)i * CONV_DIM);
        // dt / dA
        dt_kernel<<<(MROWS * NHEADS + 255) / 256, 256>>>(
            dt_bias + i * NHEADS, A_log + i * NHEADS);
        // selective scan
        scan_kernel<<<BATCH * NHEADS, 256>>>(Dv, i * NHEADS);
        // gate + rmsnorm
        gate_rms_kernel<<<MROWS, 256>>>(rms_w + (long)i * D_INNER);
        // out_proj: (1024,512) = y (1024,1024) @ Wo^T
        {
            dim3 grid(D_MODEL / 64, MROWS / 64);
            gemm_btn<<<grid, 256>>>(dy, out_proj_w + (long)i * D_MODEL * D_INNER,
                                    nullptr, dy2, MROWS, D_MODEL, D_INNER);
        }
        // residual + layernorm
        res_ln_kernel<<<MROWS, 256>>>(ln_w + i * D_MODEL, ln_b + i * D_MODEL);
    }

    // head: (1024,1000) = x @ head_w^T + head_b
    {
        dim3 grid((LABELS + 63) / 64, MROWS / 64);
        gemm_btn<<<grid, 256>>>(dx, head_w, head_b, out, MROWS, LABELS, D_MODEL);
    }
}

// round 3
// speedup vs baseline: 1.0040x; 1.0040x over previous
#include <cuda_runtime.h>
#include <cuda_bf16.h>
#include <math.h>
#include <stdint.h>

// ---------------- problem constants ----------------
#define NB        2
#define D_MODEL   512
#define D_STATE   128
#define D_CONV    4
#define HEADDIM   64
#define D_INNER   1024
#define NHEADS    16
#define CONV_DIM  1280          // D_INNER + 2*D_STATE
#define D_IN_PROJ 2320          // 2*D_INNER + 2*D_STATE + NHEADS
#define NPAD_IN   2432          // 19*128
#define LABELS    1000
#define NPAD_HD   1024
#define BATCH     2
#define SEQ       512
#define MROWS     (BATCH*SEQ)   // 1024

// ---------------- scratch (no allocation allowed) ----------------
__device__ float g_x  [MROWS * D_MODEL];
__device__ float g_zx [MROWS * D_IN_PROJ];
__device__ float g_xbc[MROWS * CONV_DIM];
__device__ float g_dt [MROWS * NHEADS];
__device__ float g_dA [MROWS * NHEADS];
__device__ float g_y  [MROWS * D_INNER];
__device__ float g_y2 [MROWS * D_MODEL];

// bf16 hi/lo split buffers
__device__ __nv_bfloat16 g_wh_in [NB][NPAD_IN * D_MODEL];
__device__ __nv_bfloat16 g_wl_in [NB][NPAD_IN * D_MODEL];
__device__ __nv_bfloat16 g_wh_out[NB][D_MODEL * D_INNER];
__device__ __nv_bfloat16 g_wl_out[NB][D_MODEL * D_INNER];
__device__ __nv_bfloat16 g_wh_hd [NPAD_HD * D_MODEL];
__device__ __nv_bfloat16 g_wl_hd [NPAD_HD * D_MODEL];
__device__ __nv_bfloat16 g_ah[MROWS * D_INNER];
__device__ __nv_bfloat16 g_al[MROWS * D_INNER];

// ---------------- PTX helpers (portable sm_80+ only) ----------------
__device__ __forceinline__ uint32_t smem_u32(const void* p) {
    uint32_t a;
    asm("{ .reg .u64 t; cvta.to.shared.u64 t, %1; cvt.u32.u64 %0, t; }" : "=r"(a) : "l"(p));
    return a;
}
__device__ __forceinline__ void cpa16(uint32_t dst, const void* src) {
    asm volatile("cp.async.cg.shared.global [%0],[%1],16;" :: "r"(dst), "l"(src) : "memory");
}
__device__ __forceinline__ void cpa_commit() {
    asm volatile("cp.async.commit_group;" ::: "memory");
}
__device__ __forceinline__ void cpa_wait0() {
    asm volatile("cp.async.wait_group 0;" ::: "memory");
}
__device__ __forceinline__ void ldsm4(uint32_t& r0, uint32_t& r1, uint32_t& r2, uint32_t& r3, uint32_t addr) {
    asm volatile("ldmatrix.sync.aligned.m8n8.x4.shared.b16 {%0,%1,%2,%3},[%4];"
                 : "=r"(r0), "=r"(r1), "=r"(r2), "=r"(r3) : "r"(addr));
}
__device__ __forceinline__ void mma16816(float* d, const uint32_t* a, const uint32_t* b) {
    asm volatile(
        "mma.sync.aligned.m16n8k16.row.col.f32.bf16.bf16.f32 "
        "{%0,%1,%2,%3},{%4,%5,%6,%7},{%8,%9},{%0,%1,%2,%3};"
        : "+f"(d[0]), "+f"(d[1]), "+f"(d[2]), "+f"(d[3])
        : "r"(a[0]), "r"(a[1]), "r"(a[2]), "r"(a[3]), "r"(b[0]), "r"(b[1]));
}

// ---------------- fp32 -> (hi, lo) bf16 split (zero-pads rows >= rows) ----------------
__global__ void split_kernel(const float* __restrict__ src,
                             __nv_bfloat16* __restrict__ h,
                             __nv_bfloat16* __restrict__ l,
                             int rows, int kshift, int total) {
    int idx = blockIdx.x * blockDim.x + threadIdx.x;
    if (idx >= total) return;
    int r = idx >> kshift;
    int c = idx & ((1 << kshift) - 1);
    float v = (r < rows) ? src[((long)r << kshift) + c] : 0.f;
    __nv_bfloat16 hv = __float2bfloat16(v);
    float res = v - __bfloat162float(hv);
    h[idx] = hv;
    l[idx] = __float2bfloat16(res);
}

// ---------------- bf16 split GEMM via mma.sync ----------------
// C[M,N] = Ah@Wh^T + Ah@Wl^T + Al@Wh^T (+bias). CTA tile 128x128, warp 64x32.
// Operands K-major; weight rows pre-padded to multiples of 128.
#define SROW 80   // bytes per smem row (32 bf16 = 64B data + 16B pad)
__global__ __launch_bounds__(256) void mma_gemm(
    const __nv_bfloat16* __restrict__ Ah, const __nv_bfloat16* __restrict__ Al,
    const __nv_bfloat16* __restrict__ Wh, const __nv_bfloat16* __restrict__ Wl,
    const float* __restrict__ bias, float* __restrict__ C,
    int N, int K)
{
    __shared__ __align__(16) char smA[2][128 * SROW];
    __shared__ __align__(16) char smW[2][128 * SROW];

    int tid = threadIdx.x;
    int lane = tid & 31, wid = tid >> 5;
    int wm = wid >> 2, wn = wid & 3;     // warp grid 2x4
    int rowBase = blockIdx.y * 128;
    int colBase = blockIdx.x * 128;

    uint32_t uA = smem_u32(smA);
    uint32_t uW = smem_u32(smW);

    const __nv_bfloat16* APh[3] = {Ah, Ah, Al};
    const __nv_bfloat16* WPh[3] = {Wh, Wl, Wh};
    int kchunks = K >> 5;
    int NC = 3 * kchunks;

    // per-thread load mapping: 2 segments each for A and W per chunk
    int r0 = (tid + 0)   >> 2, s0 = (tid + 0)   & 3;
    int r1 = (tid + 256) >> 2, s1 = (tid + 256) & 3;

    float acc[4][4][4];
#pragma unroll
    for (int i = 0; i < 4; i++)
#pragma unroll
        for (int j = 0; j < 4; j++)
#pragma unroll
            for (int k = 0; k < 4; k++) acc[i][j][k] = 0.f;

    // prefetch chunk 0
    {
        const __nv_bfloat16* Ap = APh[0] + (long)rowBase * K;
        const __nv_bfloat16* Wp = WPh[0] + (long)colBase * K;
        cpa16(uA + 0 + r0 * SROW + s0 * 16, Ap + (long)r0 * K + s0 * 8);
        cpa16(uA + 0 + r1 * SROW + s1 * 16, Ap + (long)r1 * K + s1 * 8);
        cpa16(uW + 0 + r0 * SROW + s0 * 16, Wp + (long)r0 * K + s0 * 8);
        cpa16(uW + 0 + r1 * SROW + s1 * 16, Wp + (long)r1 * K + s1 * 8);
        cpa_commit();
    }

    // ldmatrix lane addressing (byte offsets inside tile)
    uint32_t aRowOff = (uint32_t)((wm * 64 + (lane & 15)) * SROW) + ((lane >> 4) ? 16u : 0u);
    uint32_t bRowOff = (uint32_t)((wn * 32 + (((lane >> 4) & 1) << 3) + (lane & 7)) * SROW)
                     + (((lane >> 3) & 1) ? 16u : 0u);

#pragma unroll 1
    for (int c = 0; c < NC; c++) {
        cpa_wait0();
        __syncthreads();

        if (c + 1 < NC) {
            int cn = c + 1;
            int ph = cn / kchunks;
            int kc = (cn - ph * kchunks) << 5;
            uint32_t stOff = (uint32_t)((cn & 1) * 128 * SROW);
            const __nv_bfloat16* Ap = APh[ph] + (long)rowBase * K + kc;
            const __nv_bfloat16* Wp = WPh[ph] + (long)colBase * K + kc;
            cpa16(uA + stOff + r0 * SROW + s0 * 16, Ap + (long)r0 * K + s0 * 8);
            cpa16(uA + stOff + r1 * SROW + s1 * 16, Ap + (long)r1 * K + s1 * 8);
            cpa16(uW + stOff + r0 * SROW + s0 * 16, Wp + (long)r0 * K + s0 * 8);
            cpa16(uW + stOff + r1 * SROW + s1 * 16, Wp + (long)r1 * K + s1 * 8);
            cpa_commit();
        }

        uint32_t stOff = (uint32_t)((c & 1) * 128 * SROW);
#pragma unroll
        for (int ks = 0; ks < 2; ks++) {
            uint32_t a[4][4];
#pragma unroll
            for (int mf = 0; mf < 4; mf++)
                ldsm4(a[mf][0], a[mf][1], a[mf][2], a[mf][3],
                      uA + stOff + aRowOff + (uint32_t)(mf * 16 * SROW) + (uint32_t)(ks * 32));
            uint32_t b[4][2];
#pragma unroll
            for (int i = 0; i < 2; i++) {
                uint32_t q0, q1, q2, q3;
                ldsm4(q0, q1, q2, q3,
                      uW + stOff + bRowOff + (uint32_t)(i * 16 * SROW) + (uint32_t)(ks * 32));
                b[i * 2 + 0][0] = q0; b[i * 2 + 0][1] = q1;
                b[i * 2 + 1][0] = q2; b[i * 2 + 1][1] = q3;
            }
#pragma unroll
            for (int mf = 0; mf < 4; mf++)
#pragma unroll
                for (int nf = 0; nf < 4; nf++)
                    mma16816(acc[mf][nf], a[mf], b[nf]);
        }
    }

    // epilogue
#pragma unroll
    for (int mf = 0; mf < 4; mf++) {
        int rr = rowBase + wm * 64 + mf * 16 + (lane >> 2);
#pragma unroll
        for (int nf = 0; nf < 4; nf++) {
            int cc = colBase + wn * 32 + nf * 8 + (lane & 3) * 2;
            if (cc < N) {
                float b0 = bias ? bias[cc] : 0.f;
                float b1 = bias ? ((cc + 1 < N) ? bias[cc + 1] : 0.f) : 0.f;
                float* p0 = C + (long)rr * N + cc;
                p0[0] = acc[mf][nf][0] + b0;
                if (cc + 1 < N) p0[1] = acc[mf][nf][1] + b1;
                float* p1 = C + (long)(rr + 8) * N + cc;
                p1[0] = acc[mf][nf][2] + b0;
                if (cc + 1 < N) p1[1] = acc[mf][nf][3] + b1;
            }
        }
    }
}

// ---------------- embedding gather ----------------
__global__ void embed_kernel(const int* __restrict__ tokens,
                             const float* __restrict__ emb) {
    int idx = blockIdx.x * blockDim.x + threadIdx.x;
    int m = idx >> 9;
    int d = idx & 511;
    g_x[idx] = emb[(long)tokens[m] * D_MODEL + d];
}

// ---------------- causal conv4 + bias + SiLU ----------------
__global__ void conv_silu_kernel(const float* __restrict__ cw,
                                 const float* __restrict__ cb) {
    int idx = blockIdx.x * blockDim.x + threadIdx.x;
    if (idx >= MROWS * CONV_DIM) return;
    int c = idx % CONV_DIM;
    int m = idx / CONV_DIM;
    int b = m >> 9, l = m & 511;
    float acc = cb[c];
#pragma unroll
    for (int k = 0; k < D_CONV; k++) {
        int ls = l + k - (D_CONV - 1);
        if (ls >= 0)
            acc = fmaf(g_zx[(long)((b << 9) + ls) * D_IN_PROJ + D_INNER + c], cw[c * D_CONV + k], acc);
    }
    g_xbc[idx] = acc / (1.f + __expf(-acc));
}

// ---------------- dt / dA ----------------
__global__ void dt_kernel(const float* __restrict__ dtb,
                          const float* __restrict__ A_log) {
    int idx = blockIdx.x * blockDim.x + threadIdx.x;
    if (idx >= MROWS * NHEADS) return;
    int h = idx & (NHEADS - 1);
    int m = idx >> 4;
    float v = g_zx[(long)m * D_IN_PROJ + D_INNER + CONV_DIM + h] + dtb[h];
    float dt = (v > 20.f) ? v : log1pf(expf(v));
    float A = -expf(A_log[h]);
    g_dt[idx] = dt;
    g_dA[idx] = expf(dt * A);
}

// ---------------- f32x2 packed helpers ----------------
__device__ __forceinline__ unsigned long long pk2(float lo, float hi) {
    unsigned long long r;
    asm("mov.b64 %0,{%1,%2};" : "=l"(r) : "f"(lo), "f"(hi));
    return r;
}
__device__ __forceinline__ void upk2(unsigned long long v, float& lo, float& hi) {
    asm("mov.b64 {%0,%1},%2;" : "=f"(lo), "=f"(hi) : "l"(v));
}
__device__ __forceinline__ unsigned long long fma2(unsigned long long a, unsigned long long b, unsigned long long c) {
    unsigned long long d;
    asm("fma.rn.f32x2 %0,%1,%2,%3;" : "=l"(d) : "l"(a), "l"(b), "l"(c));
    return d;
}
__device__ __forceinline__ unsigned long long mul2(unsigned long long a, unsigned long long b) {
    unsigned long long d;
    asm("mul.rn.f32x2 %0,%1,%2;" : "=l"(d) : "l"(a), "l"(b));
    return d;
}

// ---------------- sequential selective scan ----------------
#define PF 8
__global__ __launch_bounds__(256) void scan_kernel(const float* __restrict__ Dv,
                                                   int layer_head_off) {
    int bh = blockIdx.x;
    int b = bh >> 4, h = bh & 15;
    int t = threadIdx.x;
    int q = t & 3, p = t >> 2;

    __shared__ float sB[PF][4 * 36];
    __shared__ float sC[PF][4 * 36];
    __shared__ float sx[PF][64];
    __shared__ float sdA[PF], sdt[PF];

    unsigned long long h2[16];
#pragma unroll
    for (int j = 0; j < 16; j++) h2[j] = 0ull;
    float Dval = Dv[h];

    const float* xbc_b = g_xbc + (long)(b * SEQ) * CONV_DIM;

    for (int l0 = 0; l0 < SEQ; l0 += PF) {
        for (int i = t; i < PF * 128; i += 256) {
            int s = i >> 7, n = i & 127;
            int qq = n >> 5, j = n & 31;
            sB[s][qq * 36 + j] = xbc_b[(long)(l0 + s) * CONV_DIM + D_INNER + n];
            sC[s][qq * 36 + j] = xbc_b[(long)(l0 + s) * CONV_DIM + D_INNER + D_STATE + n];
        }
        for (int i = t; i < PF * 64; i += 256) {
            int s = i >> 6, pp = i & 63;
            sx[s][pp] = xbc_b[(long)(l0 + s) * CONV_DIM + h * HEADDIM + pp];
        }
        if (t < PF) {
            int m = b * SEQ + l0 + t;
            sdA[t] = g_dA[m * NHEADS + h];
            sdt[t] = g_dt[m * NHEADS + h];
        }
        __syncthreads();

#pragma unroll
        for (int s = 0; s < PF; s++) {
            float dA = sdA[s];
            float xv = sx[s][p];
            float coef = sdt[s] * xv;
            unsigned long long dA2 = pk2(dA, dA);
            unsigned long long cf2 = pk2(coef, coef);
            const unsigned long long* B2 = (const unsigned long long*)&sB[s][q * 36];
            const unsigned long long* C2 = (const unsigned long long*)&sC[s][q * 36];
            unsigned long long acc2 = 0ull;
#pragma unroll
            for (int jj = 0; jj < 16; jj++) {
                unsigned long long b2 = B2[jj];
                unsigned long long c2 = C2[jj];
                h2[jj] = fma2(h2[jj], dA2, mul2(cf2, b2));
                acc2 = fma2(h2[jj], c2, acc2);
            }
            float alo, ahi;
            upk2(acc2, alo, ahi);
            float acc = alo + ahi;
            acc += __shfl_xor_sync(0xffffffffu, acc, 1);
            acc += __shfl_xor_sync(0xffffffffu, acc, 2);
            if (q == 0)
                g_y[(long)(b * SEQ + l0 + s) * D_INNER + h * HEADDIM + p] = acc + Dval * xv;
        }
        __syncthreads();
    }
}

// ---------------- gate + RMSNorm ----------------
__global__ __launch_bounds__(256) void gate_rms_kernel(const float* __restrict__ rw) {
    int m = blockIdx.x;
    int t = threadIdx.x;
    __shared__ float red[8];
    float vals[4];
    float ss = 0.f;
#pragma unroll
    for (int i = 0; i < 4; i++) {
        int c = t + i * 256;
        float z = g_zx[(long)m * D_IN_PROJ + c];
        float gate = z / (1.f + __expf(-z));
        float v = g_y[(long)m * D_INNER + c] * gate;
        vals[i] = v;
        ss = fmaf(v, v, ss);
    }
#pragma unroll
    for (int o = 16; o; o >>= 1) ss += __shfl_xor_sync(0xffffffffu, ss, o);
    if ((t & 31) == 0) red[t >> 5] = ss;
    __syncthreads();
    float tot = 0.f;
#pragma unroll
    for (int i = 0; i < 8; i++) tot += red[i];
    float rs = rsqrtf(tot * (1.f / D_INNER) + 1e-5f);
#pragma unroll
    for (int i = 0; i < 4; i++) {
        int c = t + i * 256;
        g_y[(long)m * D_INNER + c] = vals[i] * rs * rw[c];
    }
}

// ---------------- residual + LayerNorm ----------------
__global__ __launch_bounds__(256) void res_ln_kernel(const float* __restrict__ lw,
                                                     const float* __restrict__ lb) {
    int m = blockIdx.x;
    int t = threadIdx.x;
    __shared__ float red[8];
    float v0 = g_y2[(long)m * D_MODEL + t]       + g_x[(long)m * D_MODEL + t];
    float v1 = g_y2[(long)m * D_MODEL + t + 256] + g_x[(long)m * D_MODEL + t + 256];
    float s = v0 + v1;
#pragma unroll
    for (int o = 16; o; o >>= 1) s += __shfl_xor_sync(0xffffffffu, s, o);
    if ((t & 31) == 0) red[t >> 5] = s;
    __syncthreads();
    float tot = 0.f;
#pragma unroll
    for (int i = 0; i < 8; i++) tot += red[i];
    float mu = tot * (1.f / D_MODEL);
    __syncthreads();
    float c0 = v0 - mu, c1 = v1 - mu;
    float ss = c0 * c0 + c1 * c1;
#pragma unroll
    for (int o = 16; o; o >>= 1) ss += __shfl_xor_sync(0xffffffffu, ss, o);
    if ((t & 31) == 0) red[t >> 5] = ss;
    __syncthreads();
    float vtot = 0.f;
#pragma unroll
    for (int i = 0; i < 8; i++) vtot += red[i];
    float rs = rsqrtf(vtot * (1.f / D_MODEL) + 1e-5f);
    g_x[(long)m * D_MODEL + t]       = c0 * rs * lw[t]       + lb[t];
    g_x[(long)m * D_MODEL + t + 256] = c1 * rs * lw[t + 256] + lb[t + 256];
}

// ---------------- launch ----------------
extern "C" void kernel_launch(void* const* d_in, const int* in_sizes, int n_in,
                              void* d_out, int out_size) {
    const int*   tokens    = (const int*)  d_in[0];
    const float* embedding = (const float*)d_in[1];
    const float* in_proj_w = (const float*)d_in[2];
    const float* conv_w    = (const float*)d_in[3];
    const float* conv_b    = (const float*)d_in[4];
    const float* dt_bias   = (const float*)d_in[5];
    const float* A_log     = (const float*)d_in[6];
    const float* Dv        = (const float*)d_in[7];
    const float* rms_w     = (const float*)d_in[8];
    const float* out_proj_w= (const float*)d_in[9];
    const float* ln_w      = (const float*)d_in[10];
    const float* ln_b      = (const float*)d_in[11];
    const float* head_w    = (const float*)d_in[12];
    const float* head_b    = (const float*)d_in[13];
    float* out = (float*)d_out;

    void *p_x, *p_zx, *p_y, *p_y2, *p_ah, *p_al;
    void *p_whin, *p_wlin, *p_whout, *p_wlout, *p_whhd, *p_wlhd;
    cudaGetSymbolAddress(&p_x,  g_x);
    cudaGetSymbolAddress(&p_zx, g_zx);
    cudaGetSymbolAddress(&p_y,  g_y);
    cudaGetSymbolAddress(&p_y2, g_y2);
    cudaGetSymbolAddress(&p_ah, g_ah);
    cudaGetSymbolAddress(&p_al, g_al);
    cudaGetSymbolAddress(&p_whin,  g_wh_in);
    cudaGetSymbolAddress(&p_wlin,  g_wl_in);
    cudaGetSymbolAddress(&p_whout, g_wh_out);
    cudaGetSymbolAddress(&p_wlout, g_wl_out);
    cudaGetSymbolAddress(&p_whhd,  g_wh_hd);
    cudaGetSymbolAddress(&p_wlhd,  g_wl_hd);
    float* dx  = (float*)p_x;
    float* dzx = (float*)p_zx;
    float* dy  = (float*)p_y;
    float* dy2 = (float*)p_y2;
    __nv_bfloat16* ah = (__nv_bfloat16*)p_ah;
    __nv_bfloat16* al = (__nv_bfloat16*)p_al;
    __nv_bfloat16* whin  = (__nv_bfloat16*)p_whin;
    __nv_bfloat16* wlin  = (__nv_bfloat16*)p_wlin;
    __nv_bfloat16* whout = (__nv_bfloat16*)p_whout;
    __nv_bfloat16* wlout = (__nv_bfloat16*)p_wlout;
    __nv_bfloat16* whhd  = (__nv_bfloat16*)p_whhd;
    __nv_bfloat16* wlhd  = (__nv_bfloat16*)p_wlhd;

    // ---- weight splits (hi/lo bf16, zero-padded rows) ----
    for (int i = 0; i < NB; i++) {
        int tot_in = NPAD_IN * D_MODEL;
        split_kernel<<<(tot_in + 255) / 256, 256>>>(
            in_proj_w + (long)i * D_IN_PROJ * D_MODEL,
            whin + (long)i * tot_in, wlin + (long)i * tot_in,
            D_IN_PROJ, 9, tot_in);
        int tot_out = D_MODEL * D_INNER;
        split_kernel<<<(tot_out + 255) / 256, 256>>>(
            out_proj_w + (long)i * tot_out,
            whout + (long)i * tot_out, wlout + (long)i * tot_out,
            D_MODEL, 10, tot_out);
    }
    {
        int tot_hd = NPAD_HD * D_MODEL;
        split_kernel<<<(tot_hd + 255) / 256, 256>>>(head_w, whhd, wlhd, LABELS, 9, tot_hd);
    }

    // embedding
    embed_kernel<<<(MROWS * D_MODEL) / 256, 256>>>(tokens, embedding);

    for (int i = 0; i < NB; i++) {
        // split x -> bf16 hi/lo
        split_kernel<<<(MROWS * D_MODEL) / 256, 256>>>(dx, ah, al, MROWS, 9, MROWS * D_MODEL);
        // in_proj: (1024,2320) = x @ Wi^T
        {
            dim3 grid(NPAD_IN / 128, MROWS / 128);
            mma_gemm<<<grid, 256>>>(ah, al,
                whin + (long)i * NPAD_IN * D_MODEL, wlin + (long)i * NPAD_IN * D_MODEL,
                nullptr, dzx, D_IN_PROJ, D_MODEL);
        }
        conv_silu_kernel<<<(MROWS * CONV_DIM + 255) / 256, 256>>>(
            conv_w + (long)i * CONV_DIM * D_CONV, conv_b + (long)i * CONV_DIM);
        dt_kernel<<<(MROWS * NHEADS + 255) / 256, 256>>>(
            dt_bias + i * NHEADS, A_log + i * NHEADS);
        scan_kernel<<<BATCH * NHEADS, 256>>>(Dv + i * NHEADS, 0);
        gate_rms_kernel<<<MROWS, 256>>>(rms_w + (long)i * D_INNER);
        // split y -> bf16 hi/lo
        split_kernel<<<(MROWS * D_INNER) / 256, 256>>>(dy, ah, al, MROWS, 10, MROWS * D_INNER);
        // out_proj: (1024,512) = y @ Wo^T
        {
            dim3 grid(D_MODEL / 128, MROWS / 128);
            mma_gemm<<<grid, 256>>>(ah, al,
                whout + (long)i * D_MODEL * D_INNER, wlout + (long)i * D_MODEL * D_INNER,
                nullptr, dy2, D_MODEL, D_INNER);
        }
        res_ln_kernel<<<MROWS, 256>>>(ln_w + i * D_MODEL, ln_b + i * D_MODEL);
    }

    // head
    split_kernel<<<(MROWS * D_MODEL) / 256, 256>>>(dx, ah, al, MROWS, 9, MROWS * D_MODEL);
    {
        dim3 grid(NPAD_HD / 128, MROWS / 128);
        mma_gemm<<<grid, 256>>>(ah, al, whhd, wlhd, head_b, out, LABELS, D_MODEL);
    }
}

// round 4
// speedup vs baseline: 2.0494x; 2.0412x over previous
#include <cuda_runtime.h>
#include <cuda_bf16.h>
#include <math.h>
#include <stdint.h>

// ---------------- problem constants ----------------
#define NB        2
#define D_MODEL   512
#define D_STATE   128
#define D_CONV    4
#define HEADDIM   64
#define D_INNER   1024
#define NHEADS    16
#define CONV_DIM  1280
#define D_IN_PROJ 2320
#define NPAD_IN   2432          // 19*128
#define LABELS    1000
#define NPAD_HD   1024
#define BATCH     2
#define SEQ       512
#define MROWS     (BATCH*SEQ)   // 1024
#define QCH       64            // scan chunk length
#define NCHUNK    (SEQ/QCH)     // 8
#define BH        (BATCH*NHEADS)// 32

// ---------------- scratch ----------------
__device__ float g_x  [MROWS * D_MODEL];
__device__ float g_zx [MROWS * D_IN_PROJ];
__device__ float g_xbc[MROWS * CONV_DIM];
__device__ float g_dt [MROWS * NHEADS];
__device__ float g_ldA[MROWS * NHEADS];
__device__ float g_y  [MROWS * D_INNER];
__device__ float g_y2 [MROWS * D_MODEL];
// chunked-scan scratch
__device__ float g_S   [BH * NCHUNK * HEADDIM * D_STATE];   // chunk input contributions
__device__ float g_Hs  [BH * NCHUNK * HEADDIM * D_STATE];   // chunk-start states
__device__ float g_cumL[BH * NCHUNK * QCH];
__device__ float g_eLtot[BH * NCHUNK];
// bf16 hi/lo split buffers
__device__ __nv_bfloat16 g_wh_in [NB][NPAD_IN * D_MODEL];
__device__ __nv_bfloat16 g_wl_in [NB][NPAD_IN * D_MODEL];
__device__ __nv_bfloat16 g_wh_out[NB][D_MODEL * D_INNER];
__device__ __nv_bfloat16 g_wl_out[NB][D_MODEL * D_INNER];
__device__ __nv_bfloat16 g_wh_hd [NPAD_HD * D_MODEL];
__device__ __nv_bfloat16 g_wl_hd [NPAD_HD * D_MODEL];
__device__ __nv_bfloat16 g_ah[MROWS * D_INNER];
__device__ __nv_bfloat16 g_al[MROWS * D_INNER];

// ---------------- PTX helpers (portable sm_80+ only) ----------------
__device__ __forceinline__ uint32_t smem_u32(const void* p) {
    uint32_t a;
    asm("{ .reg .u64 t; cvta.to.shared.u64 t, %1; cvt.u32.u64 %0, t; }" : "=r"(a) : "l"(p));
    return a;
}
__device__ __forceinline__ void cpa16(uint32_t dst, const void* src) {
    asm volatile("cp.async.cg.shared.global [%0],[%1],16;" :: "r"(dst), "l"(src) : "memory");
}
__device__ __forceinline__ void cpa_commit() {
    asm volatile("cp.async.commit_group;" ::: "memory");
}
template<int N> __device__ __forceinline__ void cpa_wait() {
    asm volatile("cp.async.wait_group %0;" :: "n"(N) : "memory");
}
__device__ __forceinline__ void ldsm4(uint32_t& r0, uint32_t& r1, uint32_t& r2, uint32_t& r3, uint32_t addr) {
    asm volatile("ldmatrix.sync.aligned.m8n8.x4.shared.b16 {%0,%1,%2,%3},[%4];"
                 : "=r"(r0), "=r"(r1), "=r"(r2), "=r"(r3) : "r"(addr));
}
__device__ __forceinline__ void mma16816(float* d, const uint32_t* a, const uint32_t* b) {
    asm volatile(
        "mma.sync.aligned.m16n8k16.row.col.f32.bf16.bf16.f32 "
        "{%0,%1,%2,%3},{%4,%5,%6,%7},{%8,%9},{%0,%1,%2,%3};"
        : "+f"(d[0]), "+f"(d[1]), "+f"(d[2]), "+f"(d[3])
        : "r"(a[0]), "r"(a[1]), "r"(a[2]), "r"(a[3]), "r"(b[0]), "r"(b[1]));
}
__device__ __forceinline__ void split1(float v, __nv_bfloat16& h, __nv_bfloat16& l) {
    __nv_bfloat16 hv = __float2bfloat16(v);
    h = hv;
    l = __float2bfloat16(v - __bfloat162float(hv));
}

// ---------------- all weight splits in ONE kernel ----------------
#define SEG_IN  ((long)NPAD_IN * D_MODEL)     // 1245184
#define SEG_OUT ((long)D_MODEL * D_INNER)     // 524288
#define WSPLIT_TOTAL (2*SEG_IN + 2*SEG_OUT + SEG_OUT)
__global__ void wsplit_all(const float* __restrict__ inw,
                           const float* __restrict__ outw,
                           const float* __restrict__ hw) {
    long idx = (long)blockIdx.x * 256 + threadIdx.x;
    if (idx >= WSPLIT_TOTAL) return;
    const float* src; __nv_bfloat16 *dh, *dl; int rows, ksh; long off;
    if (idx < 2 * SEG_IN) {
        int layer = idx >= SEG_IN;
        off = idx - (long)layer * SEG_IN;
        src = inw + (long)layer * D_IN_PROJ * D_MODEL;
        dh = g_wh_in[layer]; dl = g_wl_in[layer]; rows = D_IN_PROJ; ksh = 9;
    } else if (idx < 2 * SEG_IN + 2 * SEG_OUT) {
        long r = idx - 2 * SEG_IN;
        int layer = r >= SEG_OUT;
        off = r - (long)layer * SEG_OUT;
        src = outw + (long)layer * SEG_OUT;
        dh = g_wh_out[layer]; dl = g_wl_out[layer]; rows = D_MODEL; ksh = 10;
    } else {
        off = idx - 2 * SEG_IN - 2 * SEG_OUT;
        src = hw; dh = g_wh_hd; dl = g_wl_hd; rows = LABELS; ksh = 9;
    }
    int r = (int)(off >> ksh), c = (int)(off & ((1 << ksh) - 1));
    float v = (r < rows) ? src[((long)r << ksh) + c] : 0.f;
    split1(v, dh[off], dl[off]);
}

// ---------------- embedding gather + split ----------------
__global__ void embed_split_kernel(const int* __restrict__ tokens,
                                   const float* __restrict__ emb) {
    int idx = blockIdx.x * blockDim.x + threadIdx.x;   // MROWS*512
    int m = idx >> 9, d = idx & 511;
    float v = emb[(long)tokens[m] * D_MODEL + d];
    g_x[idx] = v;
    split1(v, g_ah[idx], g_al[idx]);
}

// ---------------- bf16 split GEMM via mma.sync, 4-stage cp.async ----------------
#define SROW 80
#define STAGE_BYTES (2 * 128 * SROW)   // 20480: A tile then W tile
__global__ __launch_bounds__(256) void mma_gemm(
    const __nv_bfloat16* __restrict__ Ah, const __nv_bfloat16* __restrict__ Al,
    const __nv_bfloat16* __restrict__ Wh, const __nv_bfloat16* __restrict__ Wl,
    const float* __restrict__ bias, float* __restrict__ C,
    int N, int K)
{
    extern __shared__ __align__(16) char dsm[];
    int tid = threadIdx.x;
    int lane = tid & 31, wid = tid >> 5;
    int wm = wid >> 2, wn = wid & 3;
    int rowBase = blockIdx.y * 128;
    int colBase = blockIdx.x * 128;
    uint32_t uDyn = smem_u32(dsm);

    const __nv_bfloat16* APh[3] = {Ah, Ah, Al};
    const __nv_bfloat16* WPh[3] = {Wh, Wl, Wh};
    int kchunks = K >> 5;
    int NCL = 3 * kchunks;

    int r0 = (tid + 0)   >> 2, s0 = (tid + 0)   & 3;
    int r1 = (tid + 256) >> 2, s1 = (tid + 256) & 3;

    float acc[4][4][4];
#pragma unroll
    for (int i = 0; i < 4; i++)
#pragma unroll
        for (int j = 0; j < 4; j++)
#pragma unroll
            for (int k = 0; k < 4; k++) acc[i][j][k] = 0.f;

    // prologue: prefetch chunks 0..2 into stages 0..2
#pragma unroll
    for (int pc = 0; pc < 3; pc++) {
        const __nv_bfloat16* Ap = APh[0] + (long)rowBase * K + (pc << 5);
        const __nv_bfloat16* Wp = WPh[0] + (long)colBase * K + (pc << 5);
        uint32_t uS = uDyn + pc * STAGE_BYTES;
        cpa16(uS + r0 * SROW + s0 * 16, Ap + (long)r0 * K + s0 * 8);
        cpa16(uS + r1 * SROW + s1 * 16, Ap + (long)r1 * K + s1 * 8);
        cpa16(uS + 128 * SROW + r0 * SROW + s0 * 16, Wp + (long)r0 * K + s0 * 8);
        cpa16(uS + 128 * SROW + r1 * SROW + s1 * 16, Wp + (long)r1 * K + s1 * 8);
        cpa_commit();
    }

    uint32_t aRowOff = (uint32_t)((wm * 64 + (lane & 15)) * SROW) + ((lane >> 4) ? 16u : 0u);
    uint32_t bRowOff = (uint32_t)((wn * 32 + (((lane >> 4) & 1) << 3) + (lane & 7)) * SROW)
                     + (((lane >> 3) & 1) ? 16u : 0u);

#pragma unroll 1
    for (int c = 0; c < NCL; c++) {
        cpa_wait<2>();
        __syncthreads();

        int cn = c + 3;
        if (cn < NCL) {
            int ph = cn / kchunks;
            int kc = (cn - ph * kchunks) << 5;
            const __nv_bfloat16* Ap = APh[ph] + (long)rowBase * K + kc;
            const __nv_bfloat16* Wp = WPh[ph] + (long)colBase * K + kc;
            uint32_t uS = uDyn + (cn & 3) * STAGE_BYTES;
            cpa16(uS + r0 * SROW + s0 * 16, Ap + (long)r0 * K + s0 * 8);
            cpa16(uS + r1 * SROW + s1 * 16, Ap + (long)r1 * K + s1 * 8);
            cpa16(uS + 128 * SROW + r0 * SROW + s0 * 16, Wp + (long)r0 * K + s0 * 8);
            cpa16(uS + 128 * SROW + r1 * SROW + s1 * 16, Wp + (long)r1 * K + s1 * 8);
        }
        cpa_commit();

        uint32_t uA = uDyn + (c & 3) * STAGE_BYTES;
        uint32_t uW = uA + 128 * SROW;
#pragma unroll
        for (int ks = 0; ks < 2; ks++) {
            uint32_t a[4][4];
#pragma unroll
            for (int mf = 0; mf < 4; mf++)
                ldsm4(a[mf][0], a[mf][1], a[mf][2], a[mf][3],
                      uA + aRowOff + (uint32_t)(mf * 16 * SROW) + (uint32_t)(ks * 32));
            uint32_t b[4][2];
#pragma unroll
            for (int i = 0; i < 2; i++) {
                uint32_t q0, q1, q2, q3;
                ldsm4(q0, q1, q2, q3,
                      uW + bRowOff + (uint32_t)(i * 16 * SROW) + (uint32_t)(ks * 32));
                b[i * 2 + 0][0] = q0; b[i * 2 + 0][1] = q1;
                b[i * 2 + 1][0] = q2; b[i * 2 + 1][1] = q3;
            }
#pragma unroll
            for (int mf = 0; mf < 4; mf++)
#pragma unroll
                for (int nf = 0; nf < 4; nf++)
                    mma16816(acc[mf][nf], a[mf], b[nf]);
        }
    }

#pragma unroll
    for (int mf = 0; mf < 4; mf++) {
        int rr = rowBase + wm * 64 + mf * 16 + (lane >> 2);
#pragma unroll
        for (int nf = 0; nf < 4; nf++) {
            int cc = colBase + wn * 32 + nf * 8 + (lane & 3) * 2;
            if (cc < N) {
                float b0 = bias ? bias[cc] : 0.f;
                float b1 = bias ? ((cc + 1 < N) ? bias[cc + 1] : 0.f) : 0.f;
                float* p0 = C + (long)rr * N + cc;
                p0[0] = acc[mf][nf][0] + b0;
                if (cc + 1 < N) p0[1] = acc[mf][nf][1] + b1;
                float* p1 = C + (long)(rr + 8) * N + cc;
                p1[0] = acc[mf][nf][2] + b0;
                if (cc + 1 < N) p1[1] = acc[mf][nf][3] + b1;
            }
        }
    }
}

// ---------------- fused causal conv4+SiLU and dt/ldA ----------------
#define CDT_COLS (CONV_DIM + NHEADS)   // 1296
__global__ void conv_dt_kernel(const float* __restrict__ cw,
                               const float* __restrict__ cb,
                               const float* __restrict__ dtb,
                               const float* __restrict__ A_log) {
    int idx = blockIdx.x * blockDim.x + threadIdx.x;
    if (idx >= MROWS * CDT_COLS) return;
    int m = idx / CDT_COLS;
    int c = idx - m * CDT_COLS;
    if (c < CONV_DIM) {
        int b = m >> 9, l = m & 511;
        float acc = cb[c];
#pragma unroll
        for (int k = 0; k < D_CONV; k++) {
            int ls = l + k - (D_CONV - 1);
            if (ls >= 0)
                acc = fmaf(g_zx[(long)((b << 9) + ls) * D_IN_PROJ + D_INNER + c], cw[c * D_CONV + k], acc);
        }
        g_xbc[(long)m * CONV_DIM + c] = acc / (1.f + __expf(-acc));
    } else {
        int h = c - CONV_DIM;
        float v = g_zx[(long)m * D_IN_PROJ + D_INNER + CONV_DIM + h] + dtb[h];
        float dt = (v > 20.f) ? v : log1pf(expf(v));
        float A = -expf(A_log[h]);
        g_dt[m * NHEADS + h] = dt;
        g_ldA[m * NHEADS + h] = dt * A;
    }
}

// ---------------- chunked scan phase 1 ----------------
// grid = BH*NCHUNK (256). Per block: intra-chunk y + chunk contribution S.
__global__ __launch_bounds__(256) void scan_p1(const float* __restrict__ Dv) {
    int blk = blockIdx.x;
    int c = blk & (NCHUNK - 1), bh = blk >> 3;
    int b = bh >> 4, h = bh & 15;
    int mBase = b * SEQ + c * QCH;
    int tid = threadIdx.x;
    int ty = tid >> 4, tx = tid & 15;

    __shared__ float sx[64][68];
    __shared__ float sG[64][68];
    __shared__ float sTa[16][68];
    __shared__ float sTb[16][68];
    __shared__ float sL[64], sDt[64], sW[64];

    const float* xbc = g_xbc;

    // load x[t][p]
    {
        int t = tid >> 2, j = (tid & 3) * 16;
        const float* src = xbc + (long)(mBase + t) * CONV_DIM + h * HEADDIM + j;
#pragma unroll
        for (int q = 0; q < 4; q++) {
            float4 v = *(const float4*)(src + q * 4);
            sx[t][j + q * 4 + 0] = v.x; sx[t][j + q * 4 + 1] = v.y;
            sx[t][j + q * 4 + 2] = v.z; sx[t][j + q * 4 + 3] = v.w;
        }
    }
    if (tid < 64) {
        sDt[tid] = g_dt[(mBase + tid) * NHEADS + h];
        sL[tid]  = g_ldA[(mBase + tid) * NHEADS + h];
    }
    __syncthreads();
    if (tid == 0) {
        float r = 0.f;
#pragma unroll 1
        for (int t = 0; t < 64; t++) { r += sL[t]; sL[t] = r; }
    }
    __syncthreads();
    if (tid < 64) {
        sW[tid] = __expf(sL[63] - sL[tid]) * sDt[tid];
        g_cumL[(bh * NCHUNK + c) * QCH + tid] = sL[tid];
        if (tid == 63) g_eLtot[bh * NCHUNK + c] = __expf(sL[63]);
    }

    // ---- GEMM1: CB[t][s] = sum_n C[t][n] B[s][n] ----
    float cb[4][4];
#pragma unroll
    for (int i = 0; i < 4; i++)
#pragma unroll
        for (int j = 0; j < 4; j++) cb[i][j] = 0.f;

#pragma unroll 1
    for (int n0 = 0; n0 < D_STATE; n0 += 16) {
        __syncthreads();
        {
            int t = tid >> 2, jj = (tid & 3) * 4;
            float4 cv = *(const float4*)(xbc + (long)(mBase + t) * CONV_DIM + D_INNER + D_STATE + n0 + jj);
            sTa[jj + 0][t] = cv.x; sTa[jj + 1][t] = cv.y; sTa[jj + 2][t] = cv.z; sTa[jj + 3][t] = cv.w;
            float4 bv = *(const float4*)(xbc + (long)(mBase + t) * CONV_DIM + D_INNER + n0 + jj);
            sTb[jj + 0][t] = bv.x; sTb[jj + 1][t] = bv.y; sTb[jj + 2][t] = bv.z; sTb[jj + 3][t] = bv.w;
        }
        __syncthreads();
#pragma unroll
        for (int nn = 0; nn < 16; nn++) {
            float av[4], bv[4];
#pragma unroll
            for (int i = 0; i < 4; i++) av[i] = sTa[nn][ty * 4 + i];
#pragma unroll
            for (int j = 0; j < 4; j++) bv[j] = sTb[nn][tx * 4 + j];
#pragma unroll
            for (int i = 0; i < 4; i++)
#pragma unroll
                for (int j = 0; j < 4; j++) cb[i][j] = fmaf(av[i], bv[j], cb[i][j]);
        }
    }
    __syncthreads();
    // G[t][s] = mask(s<=t) * exp(L_t - L_s) * dt_s * CB
#pragma unroll
    for (int i = 0; i < 4; i++) {
        int t = ty * 4 + i;
#pragma unroll
        for (int j = 0; j < 4; j++) {
            int s = tx * 4 + j;
            float g = 0.f;
            if (s <= t) g = cb[i][j] * __expf(sL[t] - sL[s]) * sDt[s];
            sG[t][s] = g;
        }
    }
    __syncthreads();

    // ---- GEMM2: y[t][p] = sum_s G[t][s] x[s][p]; add D*x; write g_y ----
    {
        float yv[4][4];
#pragma unroll
        for (int i = 0; i < 4; i++)
#pragma unroll
            for (int j = 0; j < 4; j++) yv[i][j] = 0.f;
#pragma unroll 1
        for (int s = 0; s < 64; s++) {
            float av[4], bv[4];
#pragma unroll
            for (int i = 0; i < 4; i++) av[i] = sG[ty * 4 + i][s];
#pragma unroll
            for (int j = 0; j < 4; j++) bv[j] = sx[s][tx * 4 + j];
#pragma unroll
            for (int i = 0; i < 4; i++)
#pragma unroll
                for (int j = 0; j < 4; j++) yv[i][j] = fmaf(av[i], bv[j], yv[i][j]);
        }
        float Dval = Dv[h];
#pragma unroll
        for (int i = 0; i < 4; i++) {
            int t = ty * 4 + i;
#pragma unroll
            for (int j = 0; j < 4; j++) {
                int p = tx * 4 + j;
                g_y[(long)(mBase + t) * D_INNER + h * HEADDIM + p] =
                    yv[i][j] + Dval * sx[t][p];
            }
        }
    }
    __syncthreads();

    // scale x rows by w_t for the S GEMM
    {
        int t = tid >> 2, j = (tid & 3) * 16;
        float w = sW[t];
#pragma unroll
        for (int q = 0; q < 16; q++) sx[t][j + q] *= w;
    }

    // ---- GEMM3: S[p][n] = sum_t xw[t][p] B[t][n]  (two 64-col halves) ----
#pragma unroll 1
    for (int nh = 0; nh < 2; nh++) {
        float sv[4][4];
#pragma unroll
        for (int i = 0; i < 4; i++)
#pragma unroll
            for (int j = 0; j < 4; j++) sv[i][j] = 0.f;
#pragma unroll 1
        for (int kt0 = 0; kt0 < 64; kt0 += 16) {
            __syncthreads();
            {
                int tt = tid >> 4, nn = (tid & 15) * 4;
                float4 bv = *(const float4*)(xbc + (long)(mBase + kt0 + tt) * CONV_DIM + D_INNER + nh * 64 + nn);
                sTa[tt][nn + 0] = bv.x; sTa[tt][nn + 1] = bv.y;
                sTa[tt][nn + 2] = bv.z; sTa[tt][nn + 3] = bv.w;
            }
            __syncthreads();
#pragma unroll
            for (int tt = 0; tt < 16; tt++) {
                int t = kt0 + tt;
                float av[4], bv[4];
#pragma unroll
                for (int i = 0; i < 4; i++) av[i] = sx[t][ty * 4 + i];
#pragma unroll
                for (int j = 0; j < 4; j++) bv[j] = sTa[tt][tx * 4 + j];
#pragma unroll
                for (int i = 0; i < 4; i++)
#pragma unroll
                    for (int j = 0; j < 4; j++) sv[i][j] = fmaf(av[i], bv[j], sv[i][j]);
            }
        }
        long base = ((long)(bh * NCHUNK + c)) * HEADDIM * D_STATE;
#pragma unroll
        for (int i = 0; i < 4; i++) {
            int p = ty * 4 + i;
#pragma unroll
            for (int j = 0; j < 4; j++) {
                int n = nh * 64 + tx * 4 + j;
                g_S[base + (long)p * D_STATE + n] = sv[i][j];
            }
        }
    }
}

// ---------------- chunked scan phase 2: inter-chunk state recurrence ----------------
__global__ __launch_bounds__(256) void scan_p2() {
    int bh = blockIdx.x;
    int tid = threadIdx.x;
    float H[32];
#pragma unroll
    for (int k = 0; k < 32; k++) H[k] = 0.f;
#pragma unroll 1
    for (int c = 0; c < NCHUNK; c++) {
        long base = ((long)(bh * NCHUNK + c)) * HEADDIM * D_STATE;
        float el = g_eLtot[bh * NCHUNK + c];
#pragma unroll
        for (int k = 0; k < 32; k++) {
            long e = base + tid + k * 256;
            g_Hs[e] = H[k];
            H[k] = el * H[k] + g_S[e];
        }
    }
}

// ---------------- chunked scan phase 3: y += exp(L_t) * C_t . H_start ----------------
__global__ __launch_bounds__(256) void scan_p3() {
    int blk = blockIdx.x;
    int c = blk & (NCHUNK - 1), bh = blk >> 3;
    int b = bh >> 4, h = bh & 15;
    int mBase = b * SEQ + c * QCH;
    int tid = threadIdx.x;
    int ty = tid >> 4, tx = tid & 15;

    __shared__ float sTa[16][68];   // C^T tile [n][t]
    __shared__ float sTh[16][68];   // H^T tile [n][p]
    __shared__ float sEL[64];

    if (tid < 64) sEL[tid] = __expf(g_cumL[(bh * NCHUNK + c) * QCH + tid]);

    float acc[4][4];
#pragma unroll
    for (int i = 0; i < 4; i++)
#pragma unroll
        for (int j = 0; j < 4; j++) acc[i][j] = 0.f;

    long hbase = ((long)(bh * NCHUNK + c)) * HEADDIM * D_STATE;
#pragma unroll 1
    for (int n0 = 0; n0 < D_STATE; n0 += 16) {
        __syncthreads();
        {
            int t = tid >> 2, jj = (tid & 3) * 4;
            float4 cv = *(const float4*)(g_xbc + (long)(mBase + t) * CONV_DIM + D_INNER + D_STATE + n0 + jj);
            sTa[jj + 0][t] = cv.x; sTa[jj + 1][t] = cv.y; sTa[jj + 2][t] = cv.z; sTa[jj + 3][t] = cv.w;
            float4 hv = *(const float4*)(g_Hs + hbase + (long)t * D_STATE + n0 + jj);
            sTh[jj + 0][t] = hv.x; sTh[jj + 1][t] = hv.y; sTh[jj + 2][t] = hv.z; sTh[jj + 3][t] = hv.w;
        }
        __syncthreads();
#pragma unroll
        for (int nn = 0; nn < 16; nn++) {
            float av[4], bv[4];
#pragma unroll
            for (int i = 0; i < 4; i++) av[i] = sTa[nn][ty * 4 + i];
#pragma unroll
            for (int j = 0; j < 4; j++) bv[j] = sTh[nn][tx * 4 + j];
#pragma unroll
            for (int i = 0; i < 4; i++)
#pragma unroll
                for (int j = 0; j < 4; j++) acc[i][j] = fmaf(av[i], bv[j], acc[i][j]);
        }
    }
#pragma unroll
    for (int i = 0; i < 4; i++) {
        int t = ty * 4 + i;
        float e = sEL[t];
#pragma unroll
        for (int j = 0; j < 4; j++) {
            int p = tx * 4 + j;
            long idx = (long)(mBase + t) * D_INNER + h * HEADDIM + p;
            g_y[idx] += e * acc[i][j];
        }
    }
}

// ---------------- gate + RMSNorm + bf16 split ----------------
__global__ __launch_bounds__(256) void gate_rms_split(const float* __restrict__ rw) {
    int m = blockIdx.x;
    int t = threadIdx.x;
    __shared__ float red[8];
    float vals[4];
    float ss = 0.f;
#pragma unroll
    for (int i = 0; i < 4; i++) {
        int c = t + i * 256;
        float z = g_zx[(long)m * D_IN_PROJ + c];
        float gate = z / (1.f + __expf(-z));
        float v = g_y[(long)m * D_INNER + c] * gate;
        vals[i] = v;
        ss = fmaf(v, v, ss);
    }
#pragma unroll
    for (int o = 16; o; o >>= 1) ss += __shfl_xor_sync(0xffffffffu, ss, o);
    if ((t & 31) == 0) red[t >> 5] = ss;
    __syncthreads();
    float tot = 0.f;
#pragma unroll
    for (int i = 0; i < 8; i++) tot += red[i];
    float rs = rsqrtf(tot * (1.f / D_INNER) + 1e-5f);
#pragma unroll
    for (int i = 0; i < 4; i++) {
        int c = t + i * 256;
        float v = vals[i] * rs * rw[c];
        split1(v, g_ah[(long)m * D_INNER + c], g_al[(long)m * D_INNER + c]);
    }
}

// ---------------- residual + LayerNorm + bf16 split ----------------
__global__ __launch_bounds__(256) void res_ln_split(const float* __restrict__ lw,
                                                    const float* __restrict__ lb) {
    int m = blockIdx.x;
    int t = threadIdx.x;
    __shared__ float red[8];
    float v0 = g_y2[(long)m * D_MODEL + t]       + g_x[(long)m * D_MODEL + t];
    float v1 = g_y2[(long)m * D_MODEL + t + 256] + g_x[(long)m * D_MODEL + t + 256];
    float s = v0 + v1;
#pragma unroll
    for (int o = 16; o; o >>= 1) s += __shfl_xor_sync(0xffffffffu, s, o);
    if ((t & 31) == 0) red[t >> 5] = s;
    __syncthreads();
    float tot = 0.f;
#pragma unroll
    for (int i = 0; i < 8; i++) tot += red[i];
    float mu = tot * (1.f / D_MODEL);
    __syncthreads();
    float c0 = v0 - mu, c1 = v1 - mu;
    float ss = c0 * c0 + c1 * c1;
#pragma unroll
    for (int o = 16; o; o >>= 1) ss += __shfl_xor_sync(0xffffffffu, ss, o);
    if ((t & 31) == 0) red[t >> 5] = ss;
    __syncthreads();
    float vtot = 0.f;
#pragma unroll
    for (int i = 0; i < 8; i++) vtot += red[i];
    float rs = rsqrtf(vtot * (1.f / D_MODEL) + 1e-5f);
    float o0 = c0 * rs * lw[t]       + lb[t];
    float o1 = c1 * rs * lw[t + 256] + lb[t + 256];
    g_x[(long)m * D_MODEL + t]       = o0;
    g_x[(long)m * D_MODEL + t + 256] = o1;
    split1(o0, g_ah[(long)m * D_MODEL + t],       g_al[(long)m * D_MODEL + t]);
    split1(o1, g_ah[(long)m * D_MODEL + t + 256], g_al[(long)m * D_MODEL + t + 256]);
}

// ---------------- launch ----------------
#define GEMM_DSM (4 * STAGE_BYTES)   // 81920
extern "C" void kernel_launch(void* const* d_in, const int* in_sizes, int n_in,
                              void* d_out, int out_size) {
    const int*   tokens    = (const int*)  d_in[0];
    const float* embedding = (const float*)d_in[1];
    const float* in_proj_w = (const float*)d_in[2];
    const float* conv_w    = (const float*)d_in[3];
    const float* conv_b    = (const float*)d_in[4];
    const float* dt_bias   = (const float*)d_in[5];
    const float* A_log     = (const float*)d_in[6];
    const float* Dv        = (const float*)d_in[7];
    const float* rms_w     = (const float*)d_in[8];
    const float* out_proj_w= (const float*)d_in[9];
    const float* ln_w      = (const float*)d_in[10];
    const float* ln_b      = (const float*)d_in[11];
    const float* head_w    = (const float*)d_in[12];
    const float* head_b    = (const float*)d_in[13];
    float* out = (float*)d_out;

    cudaFuncSetAttribute(mma_gemm, cudaFuncAttributeMaxDynamicSharedMemorySize, GEMM_DSM);

    void *p_zx, *p_y, *p_y2, *p_ah, *p_al;
    void *p_whin, *p_wlin, *p_whout, *p_wlout, *p_whhd, *p_wlhd;
    cudaGetSymbolAddress(&p_zx, g_zx);
    cudaGetSymbolAddress(&p_y,  g_y);
    cudaGetSymbolAddress(&p_y2, g_y2);
    cudaGetSymbolAddress(&p_ah, g_ah);
    cudaGetSymbolAddress(&p_al, g_al);
    cudaGetSymbolAddress(&p_whin,  g_wh_in);
    cudaGetSymbolAddress(&p_wlin,  g_wl_in);
    cudaGetSymbolAddress(&p_whout, g_wh_out);
    cudaGetSymbolAddress(&p_wlout, g_wl_out);
    cudaGetSymbolAddress(&p_whhd,  g_wh_hd);
    cudaGetSymbolAddress(&p_wlhd,  g_wl_hd);
    float* dzx = (float*)p_zx;
    float* dy2 = (float*)p_y2;
    __nv_bfloat16* ah = (__nv_bfloat16*)p_ah;
    __nv_bfloat16* al = (__nv_bfloat16*)p_al;
    __nv_bfloat16* whin  = (__nv_bfloat16*)p_whin;
    __nv_bfloat16* wlin  = (__nv_bfloat16*)p_wlin;
    __nv_bfloat16* whout = (__nv_bfloat16*)p_whout;
    __nv_bfloat16* wlout = (__nv_bfloat16*)p_wlout;
    __nv_bfloat16* whhd  = (__nv_bfloat16*)p_whhd;
    __nv_bfloat16* wlhd  = (__nv_bfloat16*)p_wlhd;

    // 1. all weight splits
    wsplit_all<<<(int)((WSPLIT_TOTAL + 255) / 256), 256>>>(in_proj_w, out_proj_w, head_w);
    // 2. embedding + activation split
    embed_split_kernel<<<(MROWS * D_MODEL) / 256, 256>>>(tokens, embedding);

    for (int i = 0; i < NB; i++) {
        // in_proj
        {
            dim3 grid(NPAD_IN / 128, MROWS / 128);
            mma_gemm<<<grid, 256, GEMM_DSM>>>(ah, al,
                whin + (long)i * NPAD_IN * D_MODEL, wlin + (long)i * NPAD_IN * D_MODEL,
                nullptr, dzx, D_IN_PROJ, D_MODEL);
        }
        // fused conv+silu & dt/ldA
        conv_dt_kernel<<<(MROWS * CDT_COLS + 255) / 256, 256>>>(
            conv_w + (long)i * CONV_DIM * D_CONV, conv_b + (long)i * CONV_DIM,
            dt_bias + i * NHEADS, A_log + i * NHEADS);
        // chunked scan
        scan_p1<<<BH * NCHUNK, 256>>>(Dv + i * NHEADS);
        scan_p2<<<BH, 256>>>();
        scan_p3<<<BH * NCHUNK, 256>>>();
        // gate + rms + split
        gate_rms_split<<<MROWS, 256>>>(rms_w + (long)i * D_INNER);
        // out_proj
        {
            dim3 grid(D_MODEL / 128, MROWS / 128);
            mma_gemm<<<grid, 256, GEMM_DSM>>>(ah, al,
                whout + (long)i * D_MODEL * D_INNER, wlout + (long)i * D_MODEL * D_INNER,
                nullptr, dy2, D_MODEL, D_INNER);
        }
        // residual + layernorm + split
        res_ln_split<<<MROWS, 256>>>(ln_w + i * D_MODEL, ln_b + i * D_MODEL);
    }

    // head
    {
        dim3 grid(NPAD_HD / 128, MROWS / 128);
        mma_gemm<<<grid, 256, GEMM_DSM>>>(ah, al, whhd, wlhd, head_b, out, LABELS, D_MODEL);
    }
}

// round 5
// speedup vs baseline: 3.1211x; 1.5229x over previous
#include <cuda_runtime.h>
#include <cuda_bf16.h>
#include <math.h>
#include <stdint.h>

// ---------------- problem constants ----------------
#define NB        2
#define D_MODEL   512
#define D_STATE   128
#define D_CONV    4
#define HEADDIM   64
#define D_INNER   1024
#define NHEADS    16
#define CONV_DIM  1280
#define D_IN_PROJ 2320
#define NPAD_IN   2432          // 19*128
#define LABELS    1000
#define NPAD_HD   1024
#define BATCH     2
#define SEQ       512
#define MROWS     (BATCH*SEQ)   // 1024
#define QCH       64
#define NCHUNK    (SEQ/QCH)     // 8
#define BH        (BATCH*NHEADS)// 32

// ---------------- scratch ----------------
__device__ float g_x  [MROWS * D_MODEL];
__device__ float g_zx [MROWS * D_IN_PROJ];
__device__ float g_xbc[MROWS * CONV_DIM];
__device__ float g_dt [MROWS * NHEADS];
__device__ float g_ldA[MROWS * NHEADS];
__device__ float g_y  [MROWS * D_INNER];
__device__ float g_y2 [MROWS * D_MODEL];
__device__ float g_y2b[MROWS * D_MODEL];
__device__ float g_S   [BH * NCHUNK * HEADDIM * D_STATE];
__device__ float g_Hs  [BH * NCHUNK * HEADDIM * D_STATE];
__device__ float g_cumL[BH * NCHUNK * QCH];
__device__ float g_eLtot[BH * NCHUNK];
__device__ __nv_bfloat16 g_wh_in [NB][NPAD_IN * D_MODEL];
__device__ __nv_bfloat16 g_wl_in [NB][NPAD_IN * D_MODEL];
__device__ __nv_bfloat16 g_wh_out[NB][D_MODEL * D_INNER];
__device__ __nv_bfloat16 g_wl_out[NB][D_MODEL * D_INNER];
__device__ __nv_bfloat16 g_wh_hd [NPAD_HD * D_MODEL];
__device__ __nv_bfloat16 g_wl_hd [NPAD_HD * D_MODEL];
__device__ __nv_bfloat16 g_ah[MROWS * D_INNER];
__device__ __nv_bfloat16 g_al[MROWS * D_INNER];

// ---------------- PTX helpers (portable sm_80+ only) ----------------
__device__ __forceinline__ uint32_t smem_u32(const void* p) {
    uint32_t a;
    asm("{ .reg .u64 t; cvta.to.shared.u64 t, %1; cvt.u32.u64 %0, t; }" : "=r"(a) : "l"(p));
    return a;
}
__device__ __forceinline__ void cpa16(uint32_t dst, const void* src) {
    asm volatile("cp.async.cg.shared.global [%0],[%1],16;" :: "r"(dst), "l"(src) : "memory");
}
__device__ __forceinline__ void cpa_commit() {
    asm volatile("cp.async.commit_group;" ::: "memory");
}
template<int N> __device__ __forceinline__ void cpa_wait() {
    asm volatile("cp.async.wait_group %0;" :: "n"(N) : "memory");
}
__device__ __forceinline__ void ldsm4(uint32_t& r0, uint32_t& r1, uint32_t& r2, uint32_t& r3, uint32_t addr) {
    asm volatile("ldmatrix.sync.aligned.m8n8.x4.shared.b16 {%0,%1,%2,%3},[%4];"
                 : "=r"(r0), "=r"(r1), "=r"(r2), "=r"(r3) : "r"(addr));
}
__device__ __forceinline__ void mma16816(float* d, const uint32_t* a, const uint32_t* b) {
    asm volatile(
        "mma.sync.aligned.m16n8k16.row.col.f32.bf16.bf16.f32 "
        "{%0,%1,%2,%3},{%4,%5,%6,%7},{%8,%9},{%0,%1,%2,%3};"
        : "+f"(d[0]), "+f"(d[1]), "+f"(d[2]), "+f"(d[3])
        : "r"(a[0]), "r"(a[1]), "r"(a[2]), "r"(a[3]), "r"(b[0]), "r"(b[1]));
}
__device__ __forceinline__ void split1(float v, __nv_bfloat16& h, __nv_bfloat16& l) {
    __nv_bfloat16 hv = __float2bfloat16(v);
    h = hv;
    l = __float2bfloat16(v - __bfloat162float(hv));
}

// ---------------- merged weight splits + embedding ----------------
#define SEG_IN  ((long)NPAD_IN * D_MODEL)
#define SEG_OUT ((long)D_MODEL * D_INNER)
#define WSPLIT_TOTAL (2*SEG_IN + 2*SEG_OUT + SEG_OUT)
#define PREP_TOTAL (WSPLIT_TOTAL + (long)MROWS * D_MODEL)
__global__ void prep_kernel(const float* __restrict__ inw,
                            const float* __restrict__ outw,
                            const float* __restrict__ hw,
                            const int* __restrict__ tokens,
                            const float* __restrict__ emb) {
    long idx = (long)blockIdx.x * 256 + threadIdx.x;
    if (idx >= PREP_TOTAL) return;
    if (idx >= WSPLIT_TOTAL) {
        long e = idx - WSPLIT_TOTAL;
        int m = (int)(e >> 9), d = (int)(e & 511);
        float v = emb[(long)tokens[m] * D_MODEL + d];
        g_x[e] = v;
        split1(v, g_ah[e], g_al[e]);
        return;
    }
    const float* src; __nv_bfloat16 *dh, *dl; int rows, ksh; long off;
    if (idx < 2 * SEG_IN) {
        int layer = idx >= SEG_IN;
        off = idx - (long)layer * SEG_IN;
        src = inw + (long)layer * D_IN_PROJ * D_MODEL;
        dh = g_wh_in[layer]; dl = g_wl_in[layer]; rows = D_IN_PROJ; ksh = 9;
    } else if (idx < 2 * SEG_IN + 2 * SEG_OUT) {
        long r = idx - 2 * SEG_IN;
        int layer = r >= SEG_OUT;
        off = r - (long)layer * SEG_OUT;
        src = outw + (long)layer * SEG_OUT;
        dh = g_wh_out[layer]; dl = g_wl_out[layer]; rows = D_MODEL; ksh = 10;
    } else {
        off = idx - 2 * SEG_IN - 2 * SEG_OUT;
        src = hw; dh = g_wh_hd; dl = g_wl_hd; rows = LABELS; ksh = 9;
    }
    int r = (int)(off >> ksh), c = (int)(off & ((1 << ksh) - 1));
    float v = (r < rows) ? src[((long)r << ksh) + c] : 0.f;
    split1(v, dh[off], dl[off]);
}

// ---------------- single-pass split-bf16 GEMM, templated N tile ----------------
// NF=4: CTA tile 128x128; NF=2: 128x64. K chunk 32, 3-stage cp.async.
#define SROW 80
template<int NF>
__global__ __launch_bounds__(256) void mma_gemm(
    const __nv_bfloat16* __restrict__ Ah, const __nv_bfloat16* __restrict__ Al,
    const __nv_bfloat16* __restrict__ Wh, const __nv_bfloat16* __restrict__ Wl,
    const float* __restrict__ bias, float* __restrict__ C0, float* __restrict__ C1,
    int N, int ld, int kchunks, int kzOff)
{
    constexpr int BN = NF * 32;
    constexpr int SB = (256 + 2 * BN) * SROW;
    extern __shared__ __align__(16) char dsm[];

    int tid = threadIdx.x;
    int lane = tid & 31, wid = tid >> 5;
    int wm = wid >> 2, wn = wid & 3;
    int rowBase = blockIdx.y * 128;
    int colBase = blockIdx.x * BN;
    int z = blockIdx.z;
    float* C = z ? C1 : C0;
    uint32_t uDyn = smem_u32(dsm);

    const __nv_bfloat16* Ahp = Ah + (long)rowBase * ld + (long)z * kzOff;
    const __nv_bfloat16* Alp = Al + (long)rowBase * ld + (long)z * kzOff;
    const __nv_bfloat16* Whp = Wh + (long)colBase * ld + (long)z * kzOff;
    const __nv_bfloat16* Wlp = Wl + (long)colBase * ld + (long)z * kzOff;

    int r = tid >> 2, s = tid & 3;

    float acc[4][NF][4];
#pragma unroll
    for (int i = 0; i < 4; i++)
#pragma unroll
        for (int j = 0; j < NF; j++)
#pragma unroll
            for (int k = 0; k < 4; k++) acc[i][j][k] = 0.f;

    // stage loader
    auto load_stage = [&](int cn) {
        uint32_t uS = uDyn + (uint32_t)((cn % 3) * SB);
        long kc = (long)cn * 32;
        const __nv_bfloat16* ap  = Ahp + kc;
        const __nv_bfloat16* alp = Alp + kc;
        const __nv_bfloat16* wp  = Whp + kc;
        const __nv_bfloat16* wlp = Wlp + kc;
        cpa16(uS + r * SROW + s * 16,              ap  + (long)r * ld + s * 8);
        cpa16(uS + (r + 64) * SROW + s * 16,       ap  + (long)(r + 64) * ld + s * 8);
        cpa16(uS + (128 + r) * SROW + s * 16,      alp + (long)r * ld + s * 8);
        cpa16(uS + (192 + r) * SROW + s * 16,      alp + (long)(r + 64) * ld + s * 8);
        cpa16(uS + (256 + r) * SROW + s * 16,      wp  + (long)r * ld + s * 8);
        if (NF == 4)
            cpa16(uS + (320 + r) * SROW + s * 16,  wp  + (long)(r + 64) * ld + s * 8);
        cpa16(uS + (256 + BN + r) * SROW + s * 16, wlp + (long)r * ld + s * 8);
        if (NF == 4)
            cpa16(uS + (256 + BN + 64 + r) * SROW + s * 16, wlp + (long)(r + 64) * ld + s * 8);
    };

    load_stage(0); cpa_commit();
    load_stage(1); cpa_commit();

    uint32_t aRowOff = (uint32_t)((wm * 64 + (lane & 15)) * SROW) + ((lane >> 4) ? 16u : 0u);
    uint32_t bRowOff = (uint32_t)((wn * NF * 8 + (((lane >> 4) & 1) << 3) + (lane & 7)) * SROW)
                     + (((lane >> 3) & 1) ? 16u : 0u);

#pragma unroll 1
    for (int c = 0; c < kchunks; c++) {
        cpa_wait<1>();
        __syncthreads();
        int cn = c + 2;
        if (cn < kchunks) load_stage(cn);
        cpa_commit();

        uint32_t uS  = uDyn + (uint32_t)((c % 3) * SB);
        uint32_t uAh = uS;
        uint32_t uAl = uS + 128 * SROW;
        uint32_t uWh = uS + 256 * SROW;
        uint32_t uWl = uS + (256 + BN) * SROW;
#pragma unroll
        for (int ks = 0; ks < 2; ks++) {
            uint32_t ah[4][4], al[4][4];
#pragma unroll
            for (int mf = 0; mf < 4; mf++) {
                ldsm4(ah[mf][0], ah[mf][1], ah[mf][2], ah[mf][3],
                      uAh + aRowOff + (uint32_t)(mf * 16 * SROW) + (uint32_t)(ks * 32));
                ldsm4(al[mf][0], al[mf][1], al[mf][2], al[mf][3],
                      uAl + aRowOff + (uint32_t)(mf * 16 * SROW) + (uint32_t)(ks * 32));
            }
            uint32_t bh[NF][2], bl[NF][2];
#pragma unroll
            for (int i = 0; i < NF / 2; i++) {
                uint32_t q0, q1, q2, q3;
                ldsm4(q0, q1, q2, q3, uWh + bRowOff + (uint32_t)(i * 16 * SROW) + (uint32_t)(ks * 32));
                bh[i * 2 + 0][0] = q0; bh[i * 2 + 0][1] = q1;
                bh[i * 2 + 1][0] = q2; bh[i * 2 + 1][1] = q3;
                ldsm4(q0, q1, q2, q3, uWl + bRowOff + (uint32_t)(i * 16 * SROW) + (uint32_t)(ks * 32));
                bl[i * 2 + 0][0] = q0; bl[i * 2 + 0][1] = q1;
                bl[i * 2 + 1][0] = q2; bl[i * 2 + 1][1] = q3;
            }
#pragma unroll
            for (int mf = 0; mf < 4; mf++)
#pragma unroll
                for (int nf = 0; nf < NF; nf++) {
                    mma16816(acc[mf][nf], ah[mf], bh[nf]);
                    mma16816(acc[mf][nf], ah[mf], bl[nf]);
                    mma16816(acc[mf][nf], al[mf], bh[nf]);
                }
        }
    }

#pragma unroll
    for (int mf = 0; mf < 4; mf++) {
        int rr = rowBase + wm * 64 + mf * 16 + (lane >> 2);
#pragma unroll
        for (int nf = 0; nf < NF; nf++) {
            int cc = colBase + wn * NF * 8 + nf * 8 + (lane & 3) * 2;
            if (cc < N) {
                float b0 = bias ? bias[cc] : 0.f;
                float b1 = bias ? ((cc + 1 < N) ? bias[cc + 1] : 0.f) : 0.f;
                float* p0 = C + (long)rr * N + cc;
                p0[0] = acc[mf][nf][0] + b0;
                if (cc + 1 < N) p0[1] = acc[mf][nf][1] + b1;
                float* p1 = C + (long)(rr + 8) * N + cc;
                p1[0] = acc[mf][nf][2] + b0;
                if (cc + 1 < N) p1[1] = acc[mf][nf][3] + b1;
            }
        }
    }
}

// ---------------- fused causal conv4+SiLU and dt/ldA ----------------
#define CDT_COLS (CONV_DIM + NHEADS)
__global__ void conv_dt_kernel(const float* __restrict__ cw,
                               const float* __restrict__ cb,
                               const float* __restrict__ dtb,
                               const float* __restrict__ A_log) {
    int idx = blockIdx.x * blockDim.x + threadIdx.x;
    if (idx >= MROWS * CDT_COLS) return;
    int m = idx / CDT_COLS;
    int c = idx - m * CDT_COLS;
    if (c < CONV_DIM) {
        int b = m >> 9, l = m & 511;
        float acc = cb[c];
#pragma unroll
        for (int k = 0; k < D_CONV; k++) {
            int ls = l + k - (D_CONV - 1);
            if (ls >= 0)
                acc = fmaf(g_zx[(long)((b << 9) + ls) * D_IN_PROJ + D_INNER + c], cw[c * D_CONV + k], acc);
        }
        g_xbc[(long)m * CONV_DIM + c] = acc / (1.f + __expf(-acc));
    } else {
        int h = c - CONV_DIM;
        float v = g_zx[(long)m * D_IN_PROJ + D_INNER + CONV_DIM + h] + dtb[h];
        float dt = (v > 20.f) ? v : log1pf(expf(v));
        float A = -expf(A_log[h]);
        g_dt[m * NHEADS + h] = dt;
        g_ldA[m * NHEADS + h] = dt * A;
    }
}

// ---------------- chunked scan phase 1 ----------------
#define P1PAD 72
__global__ __launch_bounds__(256) void scan_p1(const float* __restrict__ Dv) {
    int blk = blockIdx.x;
    int c = blk & (NCHUNK - 1), bh = blk >> 3;
    int b = bh >> 4, h = bh & 15;
    int mBase = b * SEQ + c * QCH;
    int tid = threadIdx.x;
    int ty = tid >> 4, tx = tid & 15;
    int lane = tid & 31;

    __shared__ float sx[64][P1PAD];
    __shared__ float sG[64][P1PAD];
    __shared__ float sTa[16][P1PAD];
    __shared__ float sTb[16][P1PAD];
    __shared__ float sL[64], sDt[64], sW[64];

    const float* xbc = g_xbc;

    {
        int t = tid >> 2, j = (tid & 3) * 16;
        const float* src = xbc + (long)(mBase + t) * CONV_DIM + h * HEADDIM + j;
#pragma unroll
        for (int q = 0; q < 4; q++) {
            float4 v = *(const float4*)(src + q * 4);
            sx[t][j + q * 4 + 0] = v.x; sx[t][j + q * 4 + 1] = v.y;
            sx[t][j + q * 4 + 2] = v.z; sx[t][j + q * 4 + 3] = v.w;
        }
    }
    if (tid < 64) {
        sDt[tid] = g_dt[(mBase + tid) * NHEADS + h];
        sL[tid]  = g_ldA[(mBase + tid) * NHEADS + h];
    }
    __syncthreads();
    // parallel inclusive cumsum over 64 (two warps)
    if (tid < 64) {
        float v = sL[tid];
#pragma unroll
        for (int o = 1; o < 32; o <<= 1) {
            float n = __shfl_up_sync(0xffffffffu, v, o);
            if (lane >= o) v += n;
        }
        sL[tid] = v;
    }
    __syncthreads();
    if (tid >= 32 && tid < 64) {
        float add = sL[31];
        sL[tid] += add;
    }
    __syncthreads();
    if (tid < 64) {
        sW[tid] = __expf(sL[63] - sL[tid]) * sDt[tid];
        g_cumL[(bh * NCHUNK + c) * QCH + tid] = sL[tid];
        if (tid == 63) g_eLtot[bh * NCHUNK + c] = __expf(sL[63]);
    }

    // GEMM1: CB[t][s] = sum_n C[t][n] B[s][n]
    float cb[4][4];
#pragma unroll
    for (int i = 0; i < 4; i++)
#pragma unroll
        for (int j = 0; j < 4; j++) cb[i][j] = 0.f;

#pragma unroll 1
    for (int n0 = 0; n0 < D_STATE; n0 += 16) {
        __syncthreads();
        {
            int t = tid >> 2, jj = (tid & 3) * 4;
            float4 cv = *(const float4*)(xbc + (long)(mBase + t) * CONV_DIM + D_INNER + D_STATE + n0 + jj);
            sTa[jj + 0][t] = cv.x; sTa[jj + 1][t] = cv.y; sTa[jj + 2][t] = cv.z; sTa[jj + 3][t] = cv.w;
            float4 bv = *(const float4*)(xbc + (long)(mBase + t) * CONV_DIM + D_INNER + n0 + jj);
            sTb[jj + 0][t] = bv.x; sTb[jj + 1][t] = bv.y; sTb[jj + 2][t] = bv.z; sTb[jj + 3][t] = bv.w;
        }
        __syncthreads();
#pragma unroll
        for (int nn = 0; nn < 16; nn++) {
            float4 a4 = *(const float4*)&sTa[nn][ty * 4];
            float4 b4 = *(const float4*)&sTb[nn][tx * 4];
            float av[4] = {a4.x, a4.y, a4.z, a4.w};
            float bv[4] = {b4.x, b4.y, b4.z, b4.w};
#pragma unroll
            for (int i = 0; i < 4; i++)
#pragma unroll
                for (int j = 0; j < 4; j++) cb[i][j] = fmaf(av[i], bv[j], cb[i][j]);
        }
    }
    __syncthreads();
#pragma unroll
    for (int i = 0; i < 4; i++) {
        int t = ty * 4 + i;
#pragma unroll
        for (int j = 0; j < 4; j++) {
            int s2 = tx * 4 + j;
            float g = 0.f;
            if (s2 <= t) g = cb[i][j] * __expf(sL[t] - sL[s2]) * sDt[s2];
            sG[t][s2] = g;
        }
    }
    __syncthreads();

    // GEMM2: y[t][p] = sum_s G[t][s] x[s][p] + D*x
    {
        float yv[4][4];
#pragma unroll
        for (int i = 0; i < 4; i++)
#pragma unroll
            for (int j = 0; j < 4; j++) yv[i][j] = 0.f;
#pragma unroll 4
        for (int s2 = 0; s2 < 64; s2++) {
            float av[4];
#pragma unroll
            for (int i = 0; i < 4; i++) av[i] = sG[ty * 4 + i][s2];
            float4 b4 = *(const float4*)&sx[s2][tx * 4];
            float bv[4] = {b4.x, b4.y, b4.z, b4.w};
#pragma unroll
            for (int i = 0; i < 4; i++)
#pragma unroll
                for (int j = 0; j < 4; j++) yv[i][j] = fmaf(av[i], bv[j], yv[i][j]);
        }
        float Dval = Dv[h];
#pragma unroll
        for (int i = 0; i < 4; i++) {
            int t = ty * 4 + i;
#pragma unroll
            for (int j = 0; j < 4; j++) {
                int p = tx * 4 + j;
                g_y[(long)(mBase + t) * D_INNER + h * HEADDIM + p] =
                    yv[i][j] + Dval * sx[t][p];
            }
        }
    }
    __syncthreads();

    {
        int t = tid >> 2, j = (tid & 3) * 16;
        float w = sW[t];
#pragma unroll
        for (int q = 0; q < 16; q++) sx[t][j + q] *= w;
    }

    // GEMM3: S[p][n] = sum_t xw[t][p] B[t][n]
#pragma unroll 1
    for (int nh = 0; nh < 2; nh++) {
        float sv[4][4];
#pragma unroll
        for (int i = 0; i < 4; i++)
#pragma unroll
            for (int j = 0; j < 4; j++) sv[i][j] = 0.f;
#pragma unroll 1
        for (int kt0 = 0; kt0 < 64; kt0 += 16) {
            __syncthreads();
            {
                int tt = tid >> 4, nn = (tid & 15) * 4;
                float4 bv = *(const float4*)(xbc + (long)(mBase + kt0 + tt) * CONV_DIM + D_INNER + nh * 64 + nn);
                sTa[tt][nn + 0] = bv.x; sTa[tt][nn + 1] = bv.y;
                sTa[tt][nn + 2] = bv.z; sTa[tt][nn + 3] = bv.w;
            }
            __syncthreads();
#pragma unroll
            for (int tt = 0; tt < 16; tt++) {
                int t = kt0 + tt;
                float4 a4 = *(const float4*)&sx[t][ty * 4];
                float4 b4 = *(const float4*)&sTa[tt][tx * 4];
                float av[4] = {a4.x, a4.y, a4.z, a4.w};
                float bv[4] = {b4.x, b4.y, b4.z, b4.w};
#pragma unroll
                for (int i = 0; i < 4; i++)
#pragma unroll
                    for (int j = 0; j < 4; j++) sv[i][j] = fmaf(av[i], bv[j], sv[i][j]);
            }
        }
        long base = ((long)(bh * NCHUNK + c)) * HEADDIM * D_STATE;
#pragma unroll
        for (int i = 0; i < 4; i++) {
            int p = ty * 4 + i;
#pragma unroll
            for (int j = 0; j < 4; j++) {
                int n = nh * 64 + tx * 4 + j;
                g_S[base + (long)p * D_STATE + n] = sv[i][j];
            }
        }
    }
}

// ---------------- chunked scan phase 2 ----------------
__global__ __launch_bounds__(256) void scan_p2() {
    int bh = blockIdx.x;
    int tid = threadIdx.x;
    float H[32];
#pragma unroll
    for (int k = 0; k < 32; k++) H[k] = 0.f;
#pragma unroll 1
    for (int c = 0; c < NCHUNK; c++) {
        long base = ((long)(bh * NCHUNK + c)) * HEADDIM * D_STATE;
        float el = g_eLtot[bh * NCHUNK + c];
#pragma unroll
        for (int k = 0; k < 32; k++) {
            long e = base + tid + k * 256;
            g_Hs[e] = H[k];
            H[k] = el * H[k] + g_S[e];
        }
    }
}

// ---------------- chunked scan phase 3 ----------------
__global__ __launch_bounds__(256) void scan_p3() {
    int blk = blockIdx.x;
    int c = blk & (NCHUNK - 1), bh = blk >> 3;
    int b = bh >> 4, h = bh & 15;
    int mBase = b * SEQ + c * QCH;
    int tid = threadIdx.x;
    int ty = tid >> 4, tx = tid & 15;

    __shared__ float sTa[16][P1PAD];
    __shared__ float sTh[16][P1PAD];
    __shared__ float sEL[64];

    if (tid < 64) sEL[tid] = __expf(g_cumL[(bh * NCHUNK + c) * QCH + tid]);

    float acc[4][4];
#pragma unroll
    for (int i = 0; i < 4; i++)
#pragma unroll
        for (int j = 0; j < 4; j++) acc[i][j] = 0.f;

    long hbase = ((long)(bh * NCHUNK + c)) * HEADDIM * D_STATE;
#pragma unroll 1
    for (int n0 = 0; n0 < D_STATE; n0 += 16) {
        __syncthreads();
        {
            int t = tid >> 2, jj = (tid & 3) * 4;
            float4 cv = *(const float4*)(g_xbc + (long)(mBase + t) * CONV_DIM + D_INNER + D_STATE + n0 + jj);
            sTa[jj + 0][t] = cv.x; sTa[jj + 1][t] = cv.y; sTa[jj + 2][t] = cv.z; sTa[jj + 3][t] = cv.w;
            float4 hv = *(const float4*)(g_Hs + hbase + (long)t * D_STATE + n0 + jj);
            sTh[jj + 0][t] = hv.x; sTh[jj + 1][t] = hv.y; sTh[jj + 2][t] = hv.z; sTh[jj + 3][t] = hv.w;
        }
        __syncthreads();
#pragma unroll
        for (int nn = 0; nn < 16; nn++) {
            float4 a4 = *(const float4*)&sTa[nn][ty * 4];
            float4 b4 = *(const float4*)&sTh[nn][tx * 4];
            float av[4] = {a4.x, a4.y, a4.z, a4.w};
            float bv[4] = {b4.x, b4.y, b4.z, b4.w};
#pragma unroll
            for (int i = 0; i < 4; i++)
#pragma unroll
                for (int j = 0; j < 4; j++) acc[i][j] = fmaf(av[i], bv[j], acc[i][j]);
        }
    }
#pragma unroll
    for (int i = 0; i < 4; i++) {
        int t = ty * 4 + i;
        float e = sEL[t];
#pragma unroll
        for (int j = 0; j < 4; j++) {
            int p = tx * 4 + j;
            long idx = (long)(mBase + t) * D_INNER + h * HEADDIM + p;
            g_y[idx] += e * acc[i][j];
        }
    }
}

// ---------------- gate + RMSNorm + split ----------------
__global__ __launch_bounds__(256) void gate_rms_split(const float* __restrict__ rw) {
    int m = blockIdx.x;
    int t = threadIdx.x;
    __shared__ float red[8];
    float vals[4];
    float ss = 0.f;
#pragma unroll
    for (int i = 0; i < 4; i++) {
        int c = t + i * 256;
        float z = g_zx[(long)m * D_IN_PROJ + c];
        float gate = z / (1.f + __expf(-z));
        float v = g_y[(long)m * D_INNER + c] * gate;
        vals[i] = v;
        ss = fmaf(v, v, ss);
    }
#pragma unroll
    for (int o = 16; o; o >>= 1) ss += __shfl_xor_sync(0xffffffffu, ss, o);
    if ((t & 31) == 0) red[t >> 5] = ss;
    __syncthreads();
    float tot = 0.f;
#pragma unroll
    for (int i = 0; i < 8; i++) tot += red[i];
    float rs = rsqrtf(tot * (1.f / D_INNER) + 1e-5f);
#pragma unroll
    for (int i = 0; i < 4; i++) {
        int c = t + i * 256;
        float v = vals[i] * rs * rw[c];
        split1(v, g_ah[(long)m * D_INNER + c], g_al[(long)m * D_INNER + c]);
    }
}

// ---------------- residual + LayerNorm + split (sums split-K partials) ----------------
__global__ __launch_bounds__(256) void res_ln_split(const float* __restrict__ lw,
                                                    const float* __restrict__ lb) {
    int m = blockIdx.x;
    int t = threadIdx.x;
    __shared__ float red[8];
    long base = (long)m * D_MODEL;
    float v0 = g_y2[base + t]       + g_y2b[base + t]       + g_x[base + t];
    float v1 = g_y2[base + t + 256] + g_y2b[base + t + 256] + g_x[base + t + 256];
    float s = v0 + v1;
#pragma unroll
    for (int o = 16; o; o >>= 1) s += __shfl_xor_sync(0xffffffffu, s, o);
    if ((t & 31) == 0) red[t >> 5] = s;
    __syncthreads();
    float tot = 0.f;
#pragma unroll
    for (int i = 0; i < 8; i++) tot += red[i];
    float mu = tot * (1.f / D_MODEL);
    __syncthreads();
    float c0 = v0 - mu, c1 = v1 - mu;
    float ss = c0 * c0 + c1 * c1;
#pragma unroll
    for (int o = 16; o; o >>= 1) ss += __shfl_xor_sync(0xffffffffu, ss, o);
    if ((t & 31) == 0) red[t >> 5] = ss;
    __syncthreads();
    float vtot = 0.f;
#pragma unroll
    for (int i = 0; i < 8; i++) vtot += red[i];
    float rs = rsqrtf(vtot * (1.f / D_MODEL) + 1e-5f);
    float o0 = c0 * rs * lw[t]       + lb[t];
    float o1 = c1 * rs * lw[t + 256] + lb[t + 256];
    g_x[base + t]       = o0;
    g_x[base + t + 256] = o1;
    split1(o0, g_ah[base + t],       g_al[base + t]);
    split1(o1, g_ah[base + t + 256], g_al[base + t + 256]);
}

// ---------------- launch ----------------
#define DSM4 (3 * (256 + 256) * SROW)   // 122880
#define DSM2 (3 * (256 + 128) * SROW)   // 92160
extern "C" void kernel_launch(void* const* d_in, const int* in_sizes, int n_in,
                              void* d_out, int out_size) {
    const int*   tokens    = (const int*)  d_in[0];
    const float* embedding = (const float*)d_in[1];
    const float* in_proj_w = (const float*)d_in[2];
    const float* conv_w    = (const float*)d_in[3];
    const float* conv_b    = (const float*)d_in[4];
    const float* dt_bias   = (const float*)d_in[5];
    const float* A_log     = (const float*)d_in[6];
    const float* Dv        = (const float*)d_in[7];
    const float* rms_w     = (const float*)d_in[8];
    const float* out_proj_w= (const float*)d_in[9];
    const float* ln_w      = (const float*)d_in[10];
    const float* ln_b      = (const float*)d_in[11];
    const float* head_w    = (const float*)d_in[12];
    const float* head_b    = (const float*)d_in[13];
    float* out = (float*)d_out;

    cudaFuncSetAttribute(mma_gemm<4>, cudaFuncAttributeMaxDynamicSharedMemorySize, DSM4);
    cudaFuncSetAttribute(mma_gemm<2>, cudaFuncAttributeMaxDynamicSharedMemorySize, DSM2);

    void *p_zx, *p_y2, *p_y2b, *p_ah, *p_al;
    void *p_whin, *p_wlin, *p_whout, *p_wlout, *p_whhd, *p_wlhd;
    cudaGetSymbolAddress(&p_zx, g_zx);
    cudaGetSymbolAddress(&p_y2, g_y2);
    cudaGetSymbolAddress(&p_y2b, g_y2b);
    cudaGetSymbolAddress(&p_ah, g_ah);
    cudaGetSymbolAddress(&p_al, g_al);
    cudaGetSymbolAddress(&p_whin,  g_wh_in);
    cudaGetSymbolAddress(&p_wlin,  g_wl_in);
    cudaGetSymbolAddress(&p_whout, g_wh_out);
    cudaGetSymbolAddress(&p_wlout, g_wl_out);
    cudaGetSymbolAddress(&p_whhd,  g_wh_hd);
    cudaGetSymbolAddress(&p_wlhd,  g_wl_hd);
    float* dzx  = (float*)p_zx;
    float* dy2  = (float*)p_y2;
    float* dy2b = (float*)p_y2b;
    __nv_bfloat16* ah = (__nv_bfloat16*)p_ah;
    __nv_bfloat16* al = (__nv_bfloat16*)p_al;
    __nv_bfloat16* whin  = (__nv_bfloat16*)p_whin;
    __nv_bfloat16* wlin  = (__nv_bfloat16*)p_wlin;
    __nv_bfloat16* whout = (__nv_bfloat16*)p_whout;
    __nv_bfloat16* wlout = (__nv_bfloat16*)p_wlout;
    __nv_bfloat16* whhd  = (__nv_bfloat16*)p_whhd;
    __nv_bfloat16* wlhd  = (__nv_bfloat16*)p_wlhd;

    // weight splits + embedding (one launch)
    prep_kernel<<<(int)((PREP_TOTAL + 255) / 256), 256>>>(
        in_proj_w, out_proj_w, head_w, tokens, embedding);

    for (int i = 0; i < NB; i++) {
        // in_proj: 128x128 tiles, 152 CTAs
        mma_gemm<4><<<dim3(NPAD_IN / 128, MROWS / 128, 1), 256, DSM4>>>(
            ah, al, whin + (long)i * NPAD_IN * D_MODEL, wlin + (long)i * NPAD_IN * D_MODEL,
            nullptr, dzx, nullptr, D_IN_PROJ, D_MODEL, D_MODEL / 32, 0);
        conv_dt_kernel<<<(MROWS * CDT_COLS + 255) / 256, 256>>>(
            conv_w + (long)i * CONV_DIM * D_CONV, conv_b + (long)i * CONV_DIM,
            dt_bias + i * NHEADS, A_log + i * NHEADS);
        scan_p1<<<BH * NCHUNK, 256>>>(Dv + i * NHEADS);
        scan_p2<<<BH, 256>>>();
        scan_p3<<<BH * NCHUNK, 256>>>();
        gate_rms_split<<<MROWS, 256>>>(rms_w + (long)i * D_INNER);
        // out_proj: 128x64 tiles, split-K=2 -> 128 CTAs
        mma_gemm<2><<<dim3(D_MODEL / 64, MROWS / 128, 2), 256, DSM2>>>(
            ah, al, whout + (long)i * D_MODEL * D_INNER, wlout + (long)i * D_MODEL * D_INNER,
            nullptr, dy2, dy2b, D_MODEL, D_INNER, 512 / 32, 512);
        res_ln_split<<<MROWS, 256>>>(ln_w + i * D_MODEL, ln_b + i * D_MODEL);
    }

    // head: 128x64 tiles, 128 CTAs
    mma_gemm<2><<<dim3(NPAD_HD / 64, MROWS / 128, 1), 256, DSM2>>>(
        ah, al, whhd, wlhd, head_b, out, nullptr, LABELS, D_MODEL, D_MODEL / 32, 0);
}

// round 6
// speedup vs baseline: 3.1604x; 1.0126x over previous
#include <cuda_runtime.h>
#include <cuda_bf16.h>
#include <math.h>
#include <stdint.h>

// ---------------- problem constants ----------------
#define NB        2
#define D_MODEL   512
#define D_STATE   128
#define D_CONV    4
#define HEADDIM   64
#define D_INNER   1024
#define NHEADS    16
#define CONV_DIM  1280
#define D_IN_PROJ 2320
#define NPAD_IN   2432
#define LABELS    1000
#define NPAD_HD   1024
#define BATCH     2
#define SEQ       512
#define MROWS     (BATCH*SEQ)
#define QCH       64
#define NCHUNK    (SEQ/QCH)     // 8
#define BH        (BATCH*NHEADS)// 32
#define BC        (BATCH*NCHUNK)// 16

// ---------------- scratch ----------------
__device__ float g_x  [MROWS * D_MODEL];
__device__ float g_zx [MROWS * D_IN_PROJ];
__device__ float g_xbc[MROWS * CONV_DIM];
__device__ float g_dt [MROWS * NHEADS];
__device__ float g_ldA[MROWS * NHEADS];
__device__ float g_y  [MROWS * D_INNER];
__device__ float g_y2 [MROWS * D_MODEL];
__device__ float g_y2b[MROWS * D_MODEL];
__device__ float g_S   [BH * NCHUNK * HEADDIM * D_STATE];
__device__ float g_Hs  [BH * NCHUNK * HEADDIM * D_STATE];
__device__ float g_cumL[BH * NCHUNK * QCH];
__device__ float g_eLtot[BH * NCHUNK];
__device__ float g_CB  [2][BC * QCH * QCH];     // head-shared C.B^T gram (2 n-halves)
__device__ __nv_bfloat16 g_wh_in [NB][NPAD_IN * D_MODEL];
__device__ __nv_bfloat16 g_wl_in [NB][NPAD_IN * D_MODEL];
__device__ __nv_bfloat16 g_wh_out[NB][D_MODEL * D_INNER];
__device__ __nv_bfloat16 g_wl_out[NB][D_MODEL * D_INNER];
__device__ __nv_bfloat16 g_wh_hd [NPAD_HD * D_MODEL];
__device__ __nv_bfloat16 g_wl_hd [NPAD_HD * D_MODEL];
__device__ __nv_bfloat16 g_ah[MROWS * D_INNER];
__device__ __nv_bfloat16 g_al[MROWS * D_INNER];

// ---------------- PTX helpers (portable sm_80+ only) ----------------
__device__ __forceinline__ uint32_t smem_u32(const void* p) {
    uint32_t a;
    asm("{ .reg .u64 t; cvta.to.shared.u64 t, %1; cvt.u32.u64 %0, t; }" : "=r"(a) : "l"(p));
    return a;
}
__device__ __forceinline__ void cpa16(uint32_t dst, const void* src) {
    asm volatile("cp.async.cg.shared.global [%0],[%1],16;" :: "r"(dst), "l"(src) : "memory");
}
__device__ __forceinline__ void cpa_commit() {
    asm volatile("cp.async.commit_group;" ::: "memory");
}
template<int N> __device__ __forceinline__ void cpa_wait() {
    asm volatile("cp.async.wait_group %0;" :: "n"(N) : "memory");
}
__device__ __forceinline__ void ldsm4(uint32_t& r0, uint32_t& r1, uint32_t& r2, uint32_t& r3, uint32_t addr) {
    asm volatile("ldmatrix.sync.aligned.m8n8.x4.shared.b16 {%0,%1,%2,%3},[%4];"
                 : "=r"(r0), "=r"(r1), "=r"(r2), "=r"(r3) : "r"(addr));
}
__device__ __forceinline__ void mma16816(float* d, const uint32_t* a, const uint32_t* b) {
    asm volatile(
        "mma.sync.aligned.m16n8k16.row.col.f32.bf16.bf16.f32 "
        "{%0,%1,%2,%3},{%4,%5,%6,%7},{%8,%9},{%0,%1,%2,%3};"
        : "+f"(d[0]), "+f"(d[1]), "+f"(d[2]), "+f"(d[3])
        : "r"(a[0]), "r"(a[1]), "r"(a[2]), "r"(a[3]), "r"(b[0]), "r"(b[1]));
}
__device__ __forceinline__ void split1(float v, __nv_bfloat16& h, __nv_bfloat16& l) {
    __nv_bfloat16 hv = __float2bfloat16(v);
    h = hv;
    l = __float2bfloat16(v - __bfloat162float(hv));
}

// ---------------- merged weight splits + embedding ----------------
#define SEG_IN  ((long)NPAD_IN * D_MODEL)
#define SEG_OUT ((long)D_MODEL * D_INNER)
#define WSPLIT_TOTAL (2*SEG_IN + 2*SEG_OUT + SEG_OUT)
#define PREP_TOTAL (WSPLIT_TOTAL + (long)MROWS * D_MODEL)
__global__ void prep_kernel(const float* __restrict__ inw,
                            const float* __restrict__ outw,
                            const float* __restrict__ hw,
                            const int* __restrict__ tokens,
                            const float* __restrict__ emb) {
    long idx = (long)blockIdx.x * 256 + threadIdx.x;
    if (idx >= PREP_TOTAL) return;
    if (idx >= WSPLIT_TOTAL) {
        long e = idx - WSPLIT_TOTAL;
        int m = (int)(e >> 9), d = (int)(e & 511);
        float v = emb[(long)tokens[m] * D_MODEL + d];
        g_x[e] = v;
        split1(v, g_ah[e], g_al[e]);
        return;
    }
    const float* src; __nv_bfloat16 *dh, *dl; int rows, ksh; long off;
    if (idx < 2 * SEG_IN) {
        int layer = idx >= SEG_IN;
        off = idx - (long)layer * SEG_IN;
        src = inw + (long)layer * D_IN_PROJ * D_MODEL;
        dh = g_wh_in[layer]; dl = g_wl_in[layer]; rows = D_IN_PROJ; ksh = 9;
    } else if (idx < 2 * SEG_IN + 2 * SEG_OUT) {
        long r = idx - 2 * SEG_IN;
        int layer = r >= SEG_OUT;
        off = r - (long)layer * SEG_OUT;
        src = outw + (long)layer * SEG_OUT;
        dh = g_wh_out[layer]; dl = g_wl_out[layer]; rows = D_MODEL; ksh = 10;
    } else {
        off = idx - 2 * SEG_IN - 2 * SEG_OUT;
        src = hw; dh = g_wh_hd; dl = g_wl_hd; rows = LABELS; ksh = 9;
    }
    int r = (int)(off >> ksh), c = (int)(off & ((1 << ksh) - 1));
    float v = (r < rows) ? src[((long)r << ksh) + c] : 0.f;
    split1(v, dh[off], dl[off]);
}

// ---------------- single-pass split-bf16 GEMM (NF=2: 128x64 tile) ----------------
#define SROW 80
template<int NF>
__global__ __launch_bounds__(256) void mma_gemm(
    const __nv_bfloat16* __restrict__ Ah, const __nv_bfloat16* __restrict__ Al,
    const __nv_bfloat16* __restrict__ Wh, const __nv_bfloat16* __restrict__ Wl,
    const float* __restrict__ bias, float* __restrict__ C0, float* __restrict__ C1,
    int N, int ld, int kchunks, int kzOff)
{
    constexpr int BN = NF * 32;
    constexpr int SB = (256 + 2 * BN) * SROW;
    extern __shared__ __align__(16) char dsm[];

    int tid = threadIdx.x;
    int lane = tid & 31, wid = tid >> 5;
    int wm = wid >> 2, wn = wid & 3;
    int rowBase = blockIdx.y * 128;
    int colBase = blockIdx.x * BN;
    int z = blockIdx.z;
    float* C = z ? C1 : C0;
    uint32_t uDyn = smem_u32(dsm);

    const __nv_bfloat16* Ahp = Ah + (long)rowBase * ld + (long)z * kzOff;
    const __nv_bfloat16* Alp = Al + (long)rowBase * ld + (long)z * kzOff;
    const __nv_bfloat16* Whp = Wh + (long)colBase * ld + (long)z * kzOff;
    const __nv_bfloat16* Wlp = Wl + (long)colBase * ld + (long)z * kzOff;

    int r = tid >> 2, s = tid & 3;

    float acc[4][NF][4];
#pragma unroll
    for (int i = 0; i < 4; i++)
#pragma unroll
        for (int j = 0; j < NF; j++)
#pragma unroll
            for (int k = 0; k < 4; k++) acc[i][j][k] = 0.f;

    auto load_stage = [&](int cn) {
        uint32_t uS = uDyn + (uint32_t)((cn % 3) * SB);
        long kc = (long)cn * 32;
        const __nv_bfloat16* ap  = Ahp + kc;
        const __nv_bfloat16* alp = Alp + kc;
        const __nv_bfloat16* wp  = Whp + kc;
        const __nv_bfloat16* wlp = Wlp + kc;
        cpa16(uS + r * SROW + s * 16,              ap  + (long)r * ld + s * 8);
        cpa16(uS + (r + 64) * SROW + s * 16,       ap  + (long)(r + 64) * ld + s * 8);
        cpa16(uS + (128 + r) * SROW + s * 16,      alp + (long)r * ld + s * 8);
        cpa16(uS + (192 + r) * SROW + s * 16,      alp + (long)(r + 64) * ld + s * 8);
        cpa16(uS + (256 + r) * SROW + s * 16,      wp  + (long)r * ld + s * 8);
        if (NF == 4)
            cpa16(uS + (320 + r) * SROW + s * 16,  wp  + (long)(r + 64) * ld + s * 8);
        cpa16(uS + (256 + BN + r) * SROW + s * 16, wlp + (long)r * ld + s * 8);
        if (NF == 4)
            cpa16(uS + (256 + BN + 64 + r) * SROW + s * 16, wlp + (long)(r + 64) * ld + s * 8);
    };

    load_stage(0); cpa_commit();
    load_stage(1); cpa_commit();

    uint32_t aRowOff = (uint32_t)((wm * 64 + (lane & 15)) * SROW) + ((lane >> 4) ? 16u : 0u);
    uint32_t bRowOff = (uint32_t)((wn * NF * 8 + (((lane >> 4) & 1) << 3) + (lane & 7)) * SROW)
                     + (((lane >> 3) & 1) ? 16u : 0u);

#pragma unroll 1
    for (int c = 0; c < kchunks; c++) {
        cpa_wait<1>();
        __syncthreads();
        int cn = c + 2;
        if (cn < kchunks) load_stage(cn);
        cpa_commit();

        uint32_t uS  = uDyn + (uint32_t)((c % 3) * SB);
        uint32_t uAh = uS;
        uint32_t uAl = uS + 128 * SROW;
        uint32_t uWh = uS + 256 * SROW;
        uint32_t uWl = uS + (256 + BN) * SROW;
#pragma unroll
        for (int ks = 0; ks < 2; ks++) {
            uint32_t ah[4][4], al[4][4];
#pragma unroll
            for (int mf = 0; mf < 4; mf++) {
                ldsm4(ah[mf][0], ah[mf][1], ah[mf][2], ah[mf][3],
                      uAh + aRowOff + (uint32_t)(mf * 16 * SROW) + (uint32_t)(ks * 32));
                ldsm4(al[mf][0], al[mf][1], al[mf][2], al[mf][3],
                      uAl + aRowOff + (uint32_t)(mf * 16 * SROW) + (uint32_t)(ks * 32));
            }
            uint32_t bh[NF][2], bl[NF][2];
#pragma unroll
            for (int i = 0; i < NF / 2; i++) {
                uint32_t q0, q1, q2, q3;
                ldsm4(q0, q1, q2, q3, uWh + bRowOff + (uint32_t)(i * 16 * SROW) + (uint32_t)(ks * 32));
                bh[i * 2 + 0][0] = q0; bh[i * 2 + 0][1] = q1;
                bh[i * 2 + 1][0] = q2; bh[i * 2 + 1][1] = q3;
                ldsm4(q0, q1, q2, q3, uWl + bRowOff + (uint32_t)(i * 16 * SROW) + (uint32_t)(ks * 32));
                bl[i * 2 + 0][0] = q0; bl[i * 2 + 0][1] = q1;
                bl[i * 2 + 1][0] = q2; bl[i * 2 + 1][1] = q3;
            }
#pragma unroll
            for (int mf = 0; mf < 4; mf++)
#pragma unroll
                for (int nf = 0; nf < NF; nf++) {
                    mma16816(acc[mf][nf], ah[mf], bh[nf]);
                    mma16816(acc[mf][nf], ah[mf], bl[nf]);
                    mma16816(acc[mf][nf], al[mf], bh[nf]);
                }
        }
    }

#pragma unroll
    for (int mf = 0; mf < 4; mf++) {
        int rr = rowBase + wm * 64 + mf * 16 + (lane >> 2);
#pragma unroll
        for (int nf = 0; nf < NF; nf++) {
            int cc = colBase + wn * NF * 8 + nf * 8 + (lane & 3) * 2;
            if (cc < N) {
                float b0 = bias ? bias[cc] : 0.f;
                float b1 = bias ? ((cc + 1 < N) ? bias[cc + 1] : 0.f) : 0.f;
                float* p0 = C + (long)rr * N + cc;
                p0[0] = acc[mf][nf][0] + b0;
                if (cc + 1 < N) p0[1] = acc[mf][nf][1] + b1;
                float* p1 = C + (long)(rr + 8) * N + cc;
                p1[0] = acc[mf][nf][2] + b0;
                if (cc + 1 < N) p1[1] = acc[mf][nf][3] + b1;
            }
        }
    }
}

// ---------------- fused causal conv4+SiLU and dt/ldA ----------------
#define CDT_COLS (CONV_DIM + NHEADS)
__global__ void conv_dt_kernel(const float* __restrict__ cw,
                               const float* __restrict__ cb,
                               const float* __restrict__ dtb,
                               const float* __restrict__ A_log) {
    int idx = blockIdx.x * blockDim.x + threadIdx.x;
    if (idx >= MROWS * CDT_COLS) return;
    int m = idx / CDT_COLS;
    int c = idx - m * CDT_COLS;
    if (c < CONV_DIM) {
        int b = m >> 9, l = m & 511;
        float acc = cb[c];
#pragma unroll
        for (int k = 0; k < D_CONV; k++) {
            int ls = l + k - (D_CONV - 1);
            if (ls >= 0)
                acc = fmaf(g_zx[(long)((b << 9) + ls) * D_IN_PROJ + D_INNER + c], cw[c * D_CONV + k], acc);
        }
        g_xbc[(long)m * CONV_DIM + c] = acc / (1.f + __expf(-acc));
    } else {
        int h = c - CONV_DIM;
        float v = g_zx[(long)m * D_IN_PROJ + D_INNER + CONV_DIM + h] + dtb[h];
        float dt = (v > 20.f) ? v : log1pf(expf(v));
        float A = -expf(A_log[h]);
        g_dt[m * NHEADS + h] = dt;
        g_ldA[m * NHEADS + h] = dt * A;
    }
}

// ---------------- CB gram (head-shared): CB[t][s] = sum_n C[t][n] B[s][n] ----------------
// grid (BC=16, 2): blockIdx.y = n-half.
__global__ __launch_bounds__(256) void cb_kernel() {
    int blk = blockIdx.x;           // b*8 + c
    int half = blockIdx.y;
    int b = blk >> 3, c = blk & 7;
    int mBase = b * SEQ + c * QCH;
    int tid = threadIdx.x;
    int ty = tid >> 4, tx = tid & 15;

    __shared__ float sTa[16][68];
    __shared__ float sTb[16][68];

    float cbv[4][4];
#pragma unroll
    for (int i = 0; i < 4; i++)
#pragma unroll
        for (int j = 0; j < 4; j++) cbv[i][j] = 0.f;

#pragma unroll 1
    for (int n0 = 0; n0 < 64; n0 += 16) {
        __syncthreads();
        {
            int t = tid >> 2, jj = (tid & 3) * 4;
            int n = half * 64 + n0 + jj;
            float4 cv = *(const float4*)(g_xbc + (long)(mBase + t) * CONV_DIM + D_INNER + D_STATE + n);
            sTa[jj + 0][t] = cv.x; sTa[jj + 1][t] = cv.y; sTa[jj + 2][t] = cv.z; sTa[jj + 3][t] = cv.w;
            float4 bv = *(const float4*)(g_xbc + (long)(mBase + t) * CONV_DIM + D_INNER + n);
            sTb[jj + 0][t] = bv.x; sTb[jj + 1][t] = bv.y; sTb[jj + 2][t] = bv.z; sTb[jj + 3][t] = bv.w;
        }
        __syncthreads();
#pragma unroll
        for (int nn = 0; nn < 16; nn++) {
            float4 a4 = *(const float4*)&sTa[nn][ty * 4];
            float4 b4 = *(const float4*)&sTb[nn][tx * 4];
            float av[4] = {a4.x, a4.y, a4.z, a4.w};
            float bv[4] = {b4.x, b4.y, b4.z, b4.w};
#pragma unroll
            for (int i = 0; i < 4; i++)
#pragma unroll
                for (int j = 0; j < 4; j++) cbv[i][j] = fmaf(av[i], bv[j], cbv[i][j]);
        }
    }
    long base = (long)blk * (QCH * QCH);
#pragma unroll
    for (int i = 0; i < 4; i++) {
        int t = ty * 4 + i;
#pragma unroll
        for (int j = 0; j < 4; j++)
            g_CB[half][base + t * 64 + tx * 4 + j] = cbv[i][j];
    }
}

// ---------------- scan phase 1 (3 roles via blockIdx.y) ----------------
// z=0: y_local = G @ x + D*x ; z=1,2: S n-half = (w.x)^T @ B
__global__ __launch_bounds__(256) void scan_p1(const float* __restrict__ Dv) {
    int blk = blockIdx.x;           // bh*8 + c
    int z = blockIdx.y;
    int c = blk & 7, bh = blk >> 3;
    int b = bh >> 4, h = bh & 15;
    int mBase = b * SEQ + c * QCH;
    int tid = threadIdx.x;
    int ty = tid >> 4, tx = tid & 15;
    int lane = tid & 31;

    __shared__ float sA[64][68];    // x (z=0) or w-scaled x (z>0)
    __shared__ float sB2[64][68];   // G (z=0) or B half (z>0)
    __shared__ float sL[64], sDt[64];

    // load x[t][p]
    int t4 = tid >> 2, j16 = (tid & 3) * 16;
    {
        const float* src = g_xbc + (long)(mBase + t4) * CONV_DIM + h * HEADDIM + j16;
#pragma unroll
        for (int q = 0; q < 4; q++) {
            float4 v = *(const float4*)(src + q * 4);
            sA[t4][j16 + q * 4 + 0] = v.x; sA[t4][j16 + q * 4 + 1] = v.y;
            sA[t4][j16 + q * 4 + 2] = v.z; sA[t4][j16 + q * 4 + 3] = v.w;
        }
    }
    if (tid < 64) {
        sDt[tid] = g_dt[(mBase + tid) * NHEADS + h];
        sL[tid]  = g_ldA[(mBase + tid) * NHEADS + h];
    }
    __syncthreads();
    if (tid < 64) {
        float v = sL[tid];
#pragma unroll
        for (int o = 1; o < 32; o <<= 1) {
            float n = __shfl_up_sync(0xffffffffu, v, o);
            if (lane >= o) v += n;
        }
        sL[tid] = v;
    }
    __syncthreads();
    if (tid >= 32 && tid < 64) sL[tid] += sL[31];
    __syncthreads();

    if (z == 0) {
        if (tid < 64) {
            g_cumL[blk * QCH + tid] = sL[tid];
            if (tid == 63) g_eLtot[blk] = __expf(sL[63]);
        }
        // build G from head-shared CB
        long cbbase = (long)((b << 3) + c) * (QCH * QCH);
#pragma unroll
        for (int i = 0; i < 4; i++) {
            int t = ty * 4 + i;
#pragma unroll
            for (int j = 0; j < 4; j++) {
                int s2 = tx * 4 + j;
                float g = 0.f;
                if (s2 <= t) {
                    float raw = g_CB[0][cbbase + t * 64 + s2] + g_CB[1][cbbase + t * 64 + s2];
                    g = raw * __expf(sL[t] - sL[s2]) * sDt[s2];
                }
                sB2[t][s2] = g;
            }
        }
        __syncthreads();
        float yv[4][4];
#pragma unroll
        for (int i = 0; i < 4; i++)
#pragma unroll
            for (int j = 0; j < 4; j++) yv[i][j] = 0.f;
#pragma unroll 4
        for (int s2 = 0; s2 < 64; s2++) {
            float av[4];
#pragma unroll
            for (int i = 0; i < 4; i++) av[i] = sB2[ty * 4 + i][s2];
            float4 b4 = *(const float4*)&sA[s2][tx * 4];
            float bv[4] = {b4.x, b4.y, b4.z, b4.w};
#pragma unroll
            for (int i = 0; i < 4; i++)
#pragma unroll
                for (int j = 0; j < 4; j++) yv[i][j] = fmaf(av[i], bv[j], yv[i][j]);
        }
        float Dval = Dv[h];
#pragma unroll
        for (int i = 0; i < 4; i++) {
            int t = ty * 4 + i;
#pragma unroll
            for (int j = 0; j < 4; j++) {
                int p = tx * 4 + j;
                g_y[(long)(mBase + t) * D_INNER + h * HEADDIM + p] = yv[i][j] + Dval * sA[t][p];
            }
        }
    } else {
        int nh = z - 1;
        // scale x rows by w_t, load B half
        {
            float w = __expf(sL[63] - sL[t4]) * sDt[t4];
#pragma unroll
            for (int q = 0; q < 16; q++) sA[t4][j16 + q] *= w;
            const float* bsrc = g_xbc + (long)(mBase + t4) * CONV_DIM + D_INNER + nh * 64 + j16;
#pragma unroll
            for (int q = 0; q < 4; q++) {
                float4 v = *(const float4*)(bsrc + q * 4);
                sB2[t4][j16 + q * 4 + 0] = v.x; sB2[t4][j16 + q * 4 + 1] = v.y;
                sB2[t4][j16 + q * 4 + 2] = v.z; sB2[t4][j16 + q * 4 + 3] = v.w;
            }
        }
        __syncthreads();
        float sv[4][4];
#pragma unroll
        for (int i = 0; i < 4; i++)
#pragma unroll
            for (int j = 0; j < 4; j++) sv[i][j] = 0.f;
#pragma unroll 4
        for (int t = 0; t < 64; t++) {
            float4 a4 = *(const float4*)&sA[t][ty * 4];
            float4 b4 = *(const float4*)&sB2[t][tx * 4];
            float av[4] = {a4.x, a4.y, a4.z, a4.w};
            float bv[4] = {b4.x, b4.y, b4.z, b4.w};
#pragma unroll
            for (int i = 0; i < 4; i++)
#pragma unroll
                for (int j = 0; j < 4; j++) sv[i][j] = fmaf(av[i], bv[j], sv[i][j]);
        }
        long base = (long)blk * (HEADDIM * D_STATE);
#pragma unroll
        for (int i = 0; i < 4; i++) {
            int p = ty * 4 + i;
#pragma unroll
            for (int j = 0; j < 4; j++)
                g_S[base + (long)p * D_STATE + nh * 64 + tx * 4 + j] = sv[i][j];
        }
    }
}

// ---------------- scan phase 2: inter-chunk recurrence ----------------
__global__ __launch_bounds__(256) void scan_p2() {
    int bh = blockIdx.x;
    int tid = threadIdx.x;
    float H[32];
#pragma unroll
    for (int k = 0; k < 32; k++) H[k] = 0.f;
#pragma unroll 1
    for (int c = 0; c < NCHUNK; c++) {
        long base = ((long)(bh * NCHUNK + c)) * HEADDIM * D_STATE;
        float el = g_eLtot[bh * NCHUNK + c];
#pragma unroll
        for (int k = 0; k < 32; k++) {
            long e = base + tid + k * 256;
            g_Hs[e] = H[k];
            H[k] = el * H[k] + g_S[e];
        }
    }
}

// ---------------- scan phase 3: y += exp(L_t) * C_t . H_start ----------------
#define P1PAD 72
__global__ __launch_bounds__(256) void scan_p3() {
    int blk = blockIdx.x;
    int c = blk & (NCHUNK - 1), bh = blk >> 3;
    int b = bh >> 4, h = bh & 15;
    int mBase = b * SEQ + c * QCH;
    int tid = threadIdx.x;
    int ty = tid >> 4, tx = tid & 15;

    __shared__ float sTa[16][P1PAD];
    __shared__ float sTh[16][P1PAD];
    __shared__ float sEL[64];

    if (tid < 64) sEL[tid] = __expf(g_cumL[(bh * NCHUNK + c) * QCH + tid]);

    float acc[4][4];
#pragma unroll
    for (int i = 0; i < 4; i++)
#pragma unroll
        for (int j = 0; j < 4; j++) acc[i][j] = 0.f;

    long hbase = ((long)(bh * NCHUNK + c)) * HEADDIM * D_STATE;
#pragma unroll 1
    for (int n0 = 0; n0 < D_STATE; n0 += 16) {
        __syncthreads();
        {
            int t = tid >> 2, jj = (tid & 3) * 4;
            float4 cv = *(const float4*)(g_xbc + (long)(mBase + t) * CONV_DIM + D_INNER + D_STATE + n0 + jj);
            sTa[jj + 0][t] = cv.x; sTa[jj + 1][t] = cv.y; sTa[jj + 2][t] = cv.z; sTa[jj + 3][t] = cv.w;
            float4 hv = *(const float4*)(g_Hs + hbase + (long)t * D_STATE + n0 + jj);
            sTh[jj + 0][t] = hv.x; sTh[jj + 1][t] = hv.y; sTh[jj + 2][t] = hv.z; sTh[jj + 3][t] = hv.w;
        }
        __syncthreads();
#pragma unroll
        for (int nn = 0; nn < 16; nn++) {
            float4 a4 = *(const float4*)&sTa[nn][ty * 4];
            float4 b4 = *(const float4*)&sTh[nn][tx * 4];
            float av[4] = {a4.x, a4.y, a4.z, a4.w};
            float bv[4] = {b4.x, b4.y, b4.z, b4.w};
#pragma unroll
            for (int i = 0; i < 4; i++)
#pragma unroll
                for (int j = 0; j < 4; j++) acc[i][j] = fmaf(av[i], bv[j], acc[i][j]);
        }
    }
#pragma unroll
    for (int i = 0; i < 4; i++) {
        int t = ty * 4 + i;
        float e = sEL[t];
#pragma unroll
        for (int j = 0; j < 4; j++) {
            int p = tx * 4 + j;
            long idx = (long)(mBase + t) * D_INNER + h * HEADDIM + p;
            g_y[idx] += e * acc[i][j];
        }
    }
}

// ---------------- gate + RMSNorm + split ----------------
__global__ __launch_bounds__(256) void gate_rms_split(const float* __restrict__ rw) {
    int m = blockIdx.x;
    int t = threadIdx.x;
    __shared__ float red[8];
    float vals[4];
    float ss = 0.f;
#pragma unroll
    for (int i = 0; i < 4; i++) {
        int c = t + i * 256;
        float z = g_zx[(long)m * D_IN_PROJ + c];
        float gate = z / (1.f + __expf(-z));
        float v = g_y[(long)m * D_INNER + c] * gate;
        vals[i] = v;
        ss = fmaf(v, v, ss);
    }
#pragma unroll
    for (int o = 16; o; o >>= 1) ss += __shfl_xor_sync(0xffffffffu, ss, o);
    if ((t & 31) == 0) red[t >> 5] = ss;
    __syncthreads();
    float tot = 0.f;
#pragma unroll
    for (int i = 0; i < 8; i++) tot += red[i];
    float rs = rsqrtf(tot * (1.f / D_INNER) + 1e-5f);
#pragma unroll
    for (int i = 0; i < 4; i++) {
        int c = t + i * 256;
        float v = vals[i] * rs * rw[c];
        split1(v, g_ah[(long)m * D_INNER + c], g_al[(long)m * D_INNER + c]);
    }
}

// ---------------- residual + LayerNorm + split ----------------
__global__ __launch_bounds__(256) void res_ln_split(const float* __restrict__ lw,
                                                    const float* __restrict__ lb) {
    int m = blockIdx.x;
    int t = threadIdx.x;
    __shared__ float red[8];
    long base = (long)m * D_MODEL;
    float v0 = g_y2[base + t]       + g_y2b[base + t]       + g_x[base + t];
    float v1 = g_y2[base + t + 256] + g_y2b[base + t + 256] + g_x[base + t + 256];
    float s = v0 + v1;
#pragma unroll
    for (int o = 16; o; o >>= 1) s += __shfl_xor_sync(0xffffffffu, s, o);
    if ((t & 31) == 0) red[t >> 5] = s;
    __syncthreads();
    float tot = 0.f;
#pragma unroll
    for (int i = 0; i < 8; i++) tot += red[i];
    float mu = tot * (1.f / D_MODEL);
    __syncthreads();
    float c0 = v0 - mu, c1 = v1 - mu;
    float ss = c0 * c0 + c1 * c1;
#pragma unroll
    for (int o = 16; o; o >>= 1) ss += __shfl_xor_sync(0xffffffffu, ss, o);
    if ((t & 31) == 0) red[t >> 5] = ss;
    __syncthreads();
    float vtot = 0.f;
#pragma unroll
    for (int i = 0; i < 8; i++) vtot += red[i];
    float rs = rsqrtf(vtot * (1.f / D_MODEL) + 1e-5f);
    float o0 = c0 * rs * lw[t]       + lb[t];
    float o1 = c1 * rs * lw[t + 256] + lb[t + 256];
    g_x[base + t]       = o0;
    g_x[base + t + 256] = o1;
    split1(o0, g_ah[base + t],       g_al[base + t]);
    split1(o1, g_ah[base + t + 256], g_al[base + t + 256]);
}

// ---------------- launch ----------------
#define DSM2 (3 * (256 + 128) * SROW)   // 92160
extern "C" void kernel_launch(void* const* d_in, const int* in_sizes, int n_in,
                              void* d_out, int out_size) {
    const int*   tokens    = (const int*)  d_in[0];
    const float* embedding = (const float*)d_in[1];
    const float* in_proj_w = (const float*)d_in[2];
    const float* conv_w    = (const float*)d_in[3];
    const float* conv_b    = (const float*)d_in[4];
    const float* dt_bias   = (const float*)d_in[5];
    const float* A_log     = (const float*)d_in[6];
    const float* Dv        = (const float*)d_in[7];
    const float* rms_w     = (const float*)d_in[8];
    const float* out_proj_w= (const float*)d_in[9];
    const float* ln_w      = (const float*)d_in[10];
    const float* ln_b      = (const float*)d_in[11];
    const float* head_w    = (const float*)d_in[12];
    const float* head_b    = (const float*)d_in[13];
    float* out = (float*)d_out;

    cudaFuncSetAttribute(mma_gemm<2>, cudaFuncAttributeMaxDynamicSharedMemorySize, DSM2);

    void *p_zx, *p_y2, *p_y2b, *p_ah, *p_al;
    void *p_whin, *p_wlin, *p_whout, *p_wlout, *p_whhd, *p_wlhd;
    cudaGetSymbolAddress(&p_zx, g_zx);
    cudaGetSymbolAddress(&p_y2, g_y2);
    cudaGetSymbolAddress(&p_y2b, g_y2b);
    cudaGetSymbolAddress(&p_ah, g_ah);
    cudaGetSymbolAddress(&p_al, g_al);
    cudaGetSymbolAddress(&p_whin,  g_wh_in);
    cudaGetSymbolAddress(&p_wlin,  g_wl_in);
    cudaGetSymbolAddress(&p_whout, g_wh_out);
    cudaGetSymbolAddress(&p_wlout, g_wl_out);
    cudaGetSymbolAddress(&p_whhd,  g_wh_hd);
    cudaGetSymbolAddress(&p_wlhd,  g_wl_hd);
    float* dzx  = (float*)p_zx;
    float* dy2  = (float*)p_y2;
    float* dy2b = (float*)p_y2b;
    __nv_bfloat16* ah = (__nv_bfloat16*)p_ah;
    __nv_bfloat16* al = (__nv_bfloat16*)p_al;
    __nv_bfloat16* whin  = (__nv_bfloat16*)p_whin;
    __nv_bfloat16* wlin  = (__nv_bfloat16*)p_wlin;
    __nv_bfloat16* whout = (__nv_bfloat16*)p_whout;
    __nv_bfloat16* wlout = (__nv_bfloat16*)p_wlout;
    __nv_bfloat16* whhd  = (__nv_bfloat16*)p_whhd;
    __nv_bfloat16* wlhd  = (__nv_bfloat16*)p_wlhd;

    prep_kernel<<<(int)((PREP_TOTAL + 255) / 256), 256>>>(
        in_proj_w, out_proj_w, head_w, tokens, embedding);

    for (int i = 0; i < NB; i++) {
        // in_proj: 128x64 tiles -> 304 CTAs, 2 CTAs/SM
        mma_gemm<2><<<dim3(NPAD_IN / 64, MROWS / 128, 1), 256, DSM2>>>(
            ah, al, whin + (long)i * NPAD_IN * D_MODEL, wlin + (long)i * NPAD_IN * D_MODEL,
            nullptr, dzx, nullptr, D_IN_PROJ, D_MODEL, D_MODEL / 32, 0);
        conv_dt_kernel<<<(MROWS * CDT_COLS + 255) / 256, 256>>>(
            conv_w + (long)i * CONV_DIM * D_CONV, conv_b + (long)i * CONV_DIM,
            dt_bias + i * NHEADS, A_log + i * NHEADS);
        cb_kernel<<<dim3(BC, 2), 256>>>();
        scan_p1<<<dim3(BH * NCHUNK, 3), 256>>>(Dv + i * NHEADS);
        scan_p2<<<BH, 256>>>();
        scan_p3<<<BH * NCHUNK, 256>>>();
        gate_rms_split<<<MROWS, 256>>>(rms_w + (long)i * D_INNER);
        mma_gemm<2><<<dim3(D_MODEL / 64, MROWS / 128, 2), 256, DSM2>>>(
            ah, al, whout + (long)i * D_MODEL * D_INNER, wlout + (long)i * D_MODEL * D_INNER,
            nullptr, dy2, dy2b, D_MODEL, D_INNER, 512 / 32, 512);
        res_ln_split<<<MROWS, 256>>>(ln_w + i * D_MODEL, ln_b + i * D_MODEL);
    }

    mma_gemm<2><<<dim3(NPAD_HD / 64, MROWS / 128, 1), 256, DSM2>>>(
        ah, al, whhd, wlhd, head_b, out, nullptr, LABELS, D_MODEL, D_MODEL / 32, 0);
}